// round 1
// baseline (speedup 1.0000x reference)
#include <cuda_runtime.h>
#include <math.h>

#define BDIM   2
#define NSEQ   2048
#define CIN    256
#define COOR   3
#define HEADS  8
#define DHEAD  64
#define DINNER 512
#define EDIM   192
#define ESTR   196   // padded E stride in shared (floats), 4-aligned
#define PSTR   68    // padded P stride
#define BR     64
#define BC     64

// Scratch (no runtime allocation allowed)
__device__ float g_q [BDIM*HEADS*NSEQ*EDIM];
__device__ float g_k [BDIM*HEADS*NSEQ*EDIM];
__device__ float g_v [BDIM*HEADS*NSEQ*EDIM];
__device__ float g_ao[BDIM*NSEQ*DINNER*COOR];

// ---------------------------------------------------------------------------
// Kernel 1: QKV projection.  q[b,n,o,c] = sum_i W[o,i] * x[b,n,i,c]
// written straight into split-head layout: g_q[(b*H+h)*N*E + n*E + d*3 + c]
// grid: (B*N/32, DINNER/64, 3), block 256
// ---------------------------------------------------------------------------
__global__ __launch_bounds__(256) void qkv_kernel(
    const float* __restrict__ x,
    const float* __restrict__ Wq,
    const float* __restrict__ Wk,
    const float* __restrict__ Wv)
{
    __shared__ float Xs[32][96];   // [row][k*3+c]
    __shared__ float Ws[64][33];   // padded

    int wsel = blockIdx.z;
    const float* W    = (wsel == 0) ? Wq : (wsel == 1 ? Wk : Wv);
    float*       outp = (wsel == 0) ? g_q : (wsel == 1 ? g_k : g_v);

    int row0 = blockIdx.x * 32;
    int o0   = blockIdx.y * 64;
    int tid  = threadIdx.x;
    int ty   = tid >> 4;       // 0..15 -> 2 rows each
    int tx   = tid & 15;       // 0..15 -> 4 outputs each (strided by 16)

    float acc[2][4][3];
#pragma unroll
    for (int i = 0; i < 2; i++)
#pragma unroll
        for (int j = 0; j < 4; j++)
#pragma unroll
            for (int c = 0; c < 3; c++) acc[i][j][c] = 0.f;

    for (int k0 = 0; k0 < CIN; k0 += 32) {
        __syncthreads();
#pragma unroll
        for (int l = tid; l < 32 * 96; l += 256) {
            int r = l / 96, kc = l % 96;
            Xs[r][kc] = x[(size_t)(row0 + r) * (CIN * COOR) + k0 * COOR + kc];
        }
#pragma unroll
        for (int l = tid; l < 64 * 32; l += 256) {
            int o = l >> 5, k = l & 31;
            Ws[o][k] = W[(size_t)(o0 + o) * CIN + k0 + k];
        }
        __syncthreads();

#pragma unroll 8
        for (int k = 0; k < 32; k++) {
            float xv[2][3], wv[4];
#pragma unroll
            for (int i = 0; i < 2; i++) {
                xv[i][0] = Xs[2 * ty + i][k * 3 + 0];
                xv[i][1] = Xs[2 * ty + i][k * 3 + 1];
                xv[i][2] = Xs[2 * ty + i][k * 3 + 2];
            }
#pragma unroll
            for (int j = 0; j < 4; j++) wv[j] = Ws[tx + 16 * j][k];
#pragma unroll
            for (int i = 0; i < 2; i++)
#pragma unroll
                for (int j = 0; j < 4; j++)
#pragma unroll
                    for (int c = 0; c < 3; c++)
                        acc[i][j][c] += xv[i][c] * wv[j];
        }
    }

#pragma unroll
    for (int i = 0; i < 2; i++) {
        int row = row0 + 2 * ty + i;
        int b = row >> 11, n = row & (NSEQ - 1);
#pragma unroll
        for (int j = 0; j < 4; j++) {
            int o = o0 + tx + 16 * j;
            int h = o >> 6, d = o & 63;
            size_t base = (((size_t)(b * HEADS + h) * NSEQ + n) * EDIM) + d * 3;
#pragma unroll
            for (int c = 0; c < 3; c++) outp[base + c] = acc[i][j][c];
        }
    }
}

// ---------------------------------------------------------------------------
// Kernel 2: flash attention per (b,h).  grid: (N/BR, B*H), block 256
// Q tile 64xE in smem; loop 64-key tiles; online softmax; P staged via smem.
// ---------------------------------------------------------------------------
__global__ __launch_bounds__(256) void attn_kernel()
{
    extern __shared__ float sm[];
    float* Qs = sm;                     // BR * ESTR
    float* Ks = sm + BR * ESTR;         // BC * ESTR
    float* Vs = sm + 2 * BR * ESTR;     // BC * ESTR
    float* Ps = sm + 3 * BR * ESTR;     // BR * PSTR

    int bh   = blockIdx.y;
    int b    = bh >> 3, h = bh & 7;
    int row0 = blockIdx.x * BR;

    const float* qb = g_q + (size_t)bh * NSEQ * EDIM;
    const float* kb = g_k + (size_t)bh * NSEQ * EDIM;
    const float* vb = g_v + (size_t)bh * NSEQ * EDIM;

    int tid = threadIdx.x;
    int ty  = tid >> 4;    // 0..15 -> 4 query rows each
    int tx  = tid & 15;    // 0..15 -> key cols tx+16j / out cols tx+16jj

    // load Q tile (float4)
    for (int l = tid; l < BR * (EDIM / 4); l += 256) {
        int r = l / (EDIM / 4), e4 = l % (EDIM / 4);
        *(float4*)(Qs + r * ESTR + e4 * 4) =
            *(const float4*)(qb + (size_t)(row0 + r) * EDIM + e4 * 4);
    }

    float m_i[4], l_i[4], o_acc[4][12];
#pragma unroll
    for (int i = 0; i < 4; i++) {
        m_i[i] = -1e30f; l_i[i] = 0.f;
#pragma unroll
        for (int jj = 0; jj < 12; jj++) o_acc[i][jj] = 0.f;
    }

    const float scale = 0.07216878365f;   // 1/sqrt(192)

    for (int kt = 0; kt < NSEQ / BC; kt++) {
        __syncthreads();   // prior PV done (and Q load on first iter ordered below)
        for (int l = tid; l < BC * (EDIM / 4); l += 256) {
            int r = l / (EDIM / 4), e4 = l % (EDIM / 4);
            size_t g = (size_t)(kt * BC + r) * EDIM + e4 * 4;
            *(float4*)(Ks + r * ESTR + e4 * 4) = *(const float4*)(kb + g);
            *(float4*)(Vs + r * ESTR + e4 * 4) = *(const float4*)(vb + g);
        }
        __syncthreads();

        // S = Q K^T  (4x4 per thread, rows 4ty+i, cols tx+16j)
        float s[4][4];
#pragma unroll
        for (int i = 0; i < 4; i++)
#pragma unroll
            for (int j = 0; j < 4; j++) s[i][j] = 0.f;

        for (int e = 0; e < EDIM; e += 4) {
            float4 qv[4], kv[4];
#pragma unroll
            for (int i = 0; i < 4; i++)
                qv[i] = *(const float4*)(Qs + (4 * ty + i) * ESTR + e);
#pragma unroll
            for (int j = 0; j < 4; j++)
                kv[j] = *(const float4*)(Ks + (tx + 16 * j) * ESTR + e);
#pragma unroll
            for (int i = 0; i < 4; i++)
#pragma unroll
                for (int j = 0; j < 4; j++)
                    s[i][j] += qv[i].x * kv[j].x + qv[i].y * kv[j].y +
                               qv[i].z * kv[j].z + qv[i].w * kv[j].w;
        }

        // online softmax (row stats reduced over the 16 tx lanes)
#pragma unroll
        for (int i = 0; i < 4; i++) {
            float mx = -1e30f;
#pragma unroll
            for (int j = 0; j < 4; j++) { s[i][j] *= scale; mx = fmaxf(mx, s[i][j]); }
#pragma unroll
            for (int off = 1; off < 16; off <<= 1)
                mx = fmaxf(mx, __shfl_xor_sync(0xffffffffu, mx, off));
            float mnew = fmaxf(m_i[i], mx);
            float corr = __expf(m_i[i] - mnew);
            float rs = 0.f;
#pragma unroll
            for (int j = 0; j < 4; j++) {
                float p = __expf(s[i][j] - mnew);
                s[i][j] = p; rs += p;
            }
#pragma unroll
            for (int off = 1; off < 16; off <<= 1)
                rs += __shfl_xor_sync(0xffffffffu, rs, off);
            l_i[i] = l_i[i] * corr + rs;
            m_i[i] = mnew;
#pragma unroll
            for (int jj = 0; jj < 12; jj++) o_acc[i][jj] *= corr;
#pragma unroll
            for (int j = 0; j < 4; j++)
                Ps[(4 * ty + i) * PSTR + tx + 16 * j] = s[i][j];
        }
        __syncthreads();

        // O += P @ V   (rows 4ty+i, out cols tx+16jj)
#pragma unroll 4
        for (int c = 0; c < BC; c++) {
            float vv[12];
#pragma unroll
            for (int jj = 0; jj < 12; jj++)
                vv[jj] = Vs[c * ESTR + tx + 16 * jj];
#pragma unroll
            for (int i = 0; i < 4; i++) {
                float p = Ps[(4 * ty + i) * PSTR + c];
#pragma unroll
                for (int jj = 0; jj < 12; jj++)
                    o_acc[i][jj] += p * vv[jj];
            }
        }
    }

    // normalize + scatter to merged-head layout g_ao[b][n][h*64+d][c]
#pragma unroll
    for (int i = 0; i < 4; i++) {
        float inv = 1.0f / l_i[i];
        int n = row0 + 4 * ty + i;
#pragma unroll
        for (int jj = 0; jj < 12; jj++) {
            int e = tx + 16 * jj;
            int d = e / 3, cc = e - d * 3;
            g_ao[(((size_t)b * NSEQ + n) * DINNER + h * DHEAD + d) * 3 + cc] =
                o_acc[i][jj] * inv;
        }
    }
}

// ---------------------------------------------------------------------------
// Kernel 3: output projection.  out[b,n,o,c] = sum_i Wo[o,i]*ao[b,n,i,c]
// grid: (B*N/32, CIN/64), block 256
// ---------------------------------------------------------------------------
__global__ __launch_bounds__(256) void oproj_kernel(
    const float* __restrict__ Wo, float* __restrict__ out)
{
    __shared__ float Xs[32][96];
    __shared__ float Ws[64][33];

    int row0 = blockIdx.x * 32;
    int o0   = blockIdx.y * 64;
    int tid  = threadIdx.x;
    int ty   = tid >> 4, tx = tid & 15;

    float acc[2][4][3];
#pragma unroll
    for (int i = 0; i < 2; i++)
#pragma unroll
        for (int j = 0; j < 4; j++)
#pragma unroll
            for (int c = 0; c < 3; c++) acc[i][j][c] = 0.f;

    for (int k0 = 0; k0 < DINNER; k0 += 32) {
        __syncthreads();
#pragma unroll
        for (int l = tid; l < 32 * 96; l += 256) {
            int r = l / 96, kc = l % 96;
            Xs[r][kc] = g_ao[(size_t)(row0 + r) * (DINNER * COOR) + k0 * COOR + kc];
        }
#pragma unroll
        for (int l = tid; l < 64 * 32; l += 256) {
            int o = l >> 5, k = l & 31;
            Ws[o][k] = Wo[(size_t)(o0 + o) * DINNER + k0 + k];
        }
        __syncthreads();

#pragma unroll 8
        for (int k = 0; k < 32; k++) {
            float xv[2][3], wv[4];
#pragma unroll
            for (int i = 0; i < 2; i++) {
                xv[i][0] = Xs[2 * ty + i][k * 3 + 0];
                xv[i][1] = Xs[2 * ty + i][k * 3 + 1];
                xv[i][2] = Xs[2 * ty + i][k * 3 + 2];
            }
#pragma unroll
            for (int j = 0; j < 4; j++) wv[j] = Ws[tx + 16 * j][k];
#pragma unroll
            for (int i = 0; i < 2; i++)
#pragma unroll
                for (int j = 0; j < 4; j++)
#pragma unroll
                    for (int c = 0; c < 3; c++)
                        acc[i][j][c] += xv[i][c] * wv[j];
        }
    }

#pragma unroll
    for (int i = 0; i < 2; i++) {
        int row = row0 + 2 * ty + i;
#pragma unroll
        for (int j = 0; j < 4; j++) {
            int o = o0 + tx + 16 * j;
#pragma unroll
            for (int c = 0; c < 3; c++)
                out[(size_t)row * (CIN * COOR) + o * 3 + c] = acc[i][j][c];
        }
    }
}

// ---------------------------------------------------------------------------
extern "C" void kernel_launch(void* const* d_in, const int* in_sizes, int n_in,
                              void* d_out, int out_size)
{
    const float* x  = (const float*)d_in[0];
    const float* Wq = (const float*)d_in[1];
    const float* Wk = (const float*)d_in[2];
    const float* Wv = (const float*)d_in[3];
    const float* Wo = (const float*)d_in[4];
    float* out = (float*)d_out;

    const int attn_smem = (3 * BR * ESTR + BR * PSTR) * 4;  // 167936 B
    cudaFuncSetAttribute(attn_kernel,
                         cudaFuncAttributeMaxDynamicSharedMemorySize, attn_smem);

    qkv_kernel<<<dim3(BDIM * NSEQ / 32, DINNER / 64, 3), 256>>>(x, Wq, Wk, Wv);
    attn_kernel<<<dim3(NSEQ / BR, BDIM * HEADS), 256, attn_smem>>>();
    oproj_kernel<<<dim3(BDIM * NSEQ / 32, CIN / 64), 256>>>(Wo, out);
}

// round 2
// speedup vs baseline: 2.2998x; 2.2998x over previous
#include <cuda_runtime.h>
#include <math.h>

#define BDIM   2
#define NSEQ   2048
#define CIN    256
#define COOR   3
#define HEADS  8
#define DHEAD  64
#define DINNER 512
#define EDIM   192
#define ESTR   196   // smem row stride (floats): 196%32=4 -> conflict-free frags
#define PSTR   36    // per-warp P stride: 36%32=4
#define XSTR   99    // projection X-tile stride (bank fix)

// Scratch (no runtime allocation allowed)
__device__ float g_q [BDIM*HEADS*NSEQ*EDIM];
__device__ float g_k [BDIM*HEADS*NSEQ*EDIM];
__device__ float g_v [BDIM*HEADS*NSEQ*EDIM];
__device__ float g_ao[BDIM*NSEQ*DINNER*COOR];

__device__ __forceinline__ unsigned f2tf32(float x) {
    unsigned r; asm("cvt.rna.tf32.f32 %0, %1;" : "=r"(r) : "f"(x)); return r;
}

__device__ __forceinline__ void mma_tf32(float* c, const unsigned* a, const unsigned* b) {
    asm volatile(
        "mma.sync.aligned.m16n8k8.row.col.f32.tf32.tf32.f32 "
        "{%0,%1,%2,%3}, {%4,%5,%6,%7}, {%8,%9}, {%0,%1,%2,%3};"
        : "+f"(c[0]), "+f"(c[1]), "+f"(c[2]), "+f"(c[3])
        : "r"(a[0]), "r"(a[1]), "r"(a[2]), "r"(a[3]), "r"(b[0]), "r"(b[1]));
}

// ---------------------------------------------------------------------------
// Kernel 1: QKV projection (bank-conflict-fixed X tile)
// grid: (B*N/32, DINNER/64, 3), block 256
// ---------------------------------------------------------------------------
__global__ __launch_bounds__(256) void qkv_kernel(
    const float* __restrict__ x,
    const float* __restrict__ Wq,
    const float* __restrict__ Wk,
    const float* __restrict__ Wv)
{
    __shared__ float Xs[32 * XSTR];
    __shared__ float Ws[64][33];

    int wsel = blockIdx.z;
    const float* W    = (wsel == 0) ? Wq : (wsel == 1 ? Wk : Wv);
    float*       outp = (wsel == 0) ? g_q : (wsel == 1 ? g_k : g_v);

    int row0 = blockIdx.x * 32;
    int o0   = blockIdx.y * 64;
    int tid  = threadIdx.x;
    int ty   = tid >> 4;
    int tx   = tid & 15;

    float acc[2][4][3];
#pragma unroll
    for (int i = 0; i < 2; i++)
#pragma unroll
        for (int j = 0; j < 4; j++)
#pragma unroll
            for (int c = 0; c < 3; c++) acc[i][j][c] = 0.f;

    for (int k0 = 0; k0 < CIN; k0 += 32) {
        __syncthreads();
#pragma unroll
        for (int l = tid; l < 32 * 96; l += 256) {
            int r = l / 96, kc = l % 96;
            Xs[r * XSTR + kc] = x[(size_t)(row0 + r) * (CIN * COOR) + k0 * COOR + kc];
        }
#pragma unroll
        for (int l = tid; l < 64 * 32; l += 256) {
            int o = l >> 5, k = l & 31;
            Ws[o][k] = W[(size_t)(o0 + o) * CIN + k0 + k];
        }
        __syncthreads();

#pragma unroll 8
        for (int k = 0; k < 32; k++) {
            float xv[2][3], wv[4];
#pragma unroll
            for (int i = 0; i < 2; i++) {
                xv[i][0] = Xs[(2 * ty + i) * XSTR + k * 3 + 0];
                xv[i][1] = Xs[(2 * ty + i) * XSTR + k * 3 + 1];
                xv[i][2] = Xs[(2 * ty + i) * XSTR + k * 3 + 2];
            }
#pragma unroll
            for (int j = 0; j < 4; j++) wv[j] = Ws[tx + 16 * j][k];
#pragma unroll
            for (int i = 0; i < 2; i++)
#pragma unroll
                for (int j = 0; j < 4; j++)
#pragma unroll
                    for (int c = 0; c < 3; c++)
                        acc[i][j][c] += xv[i][c] * wv[j];
        }
    }

#pragma unroll
    for (int i = 0; i < 2; i++) {
        int row = row0 + 2 * ty + i;
        int b = row >> 11, n = row & (NSEQ - 1);
#pragma unroll
        for (int j = 0; j < 4; j++) {
            int o = o0 + tx + 16 * j;
            int h = o >> 6, d = o & 63;
            size_t base = (((size_t)(b * HEADS + h) * NSEQ + n) * EDIM) + d * 3;
#pragma unroll
            for (int c = 0; c < 3; c++) outp[base + c] = acc[i][j][c];
        }
    }
}

// ---------------------------------------------------------------------------
// Kernel 2: flash attention with tf32 mma.sync (m16n8k8).
// block = 128 threads (4 warps), BR=64 query rows, BC=32 key cols per tile.
// warp w owns rows [16w,16w+16); O accum (16 x 192) in C-fragments (96 regs).
// grid: (N/64, B*H)
// ---------------------------------------------------------------------------
__global__ __launch_bounds__(128, 2) void attn_mma_kernel()
{
    extern __shared__ float sm[];
    float* Qs = sm;                       // 64  * ESTR
    float* Ks = Qs + 64 * ESTR;           // 32  * ESTR
    float* Vs = Ks + 32 * ESTR;           // 32  * ESTR
    float* Ps = Vs + 32 * ESTR;           // 4 warps * 16 * PSTR

    int tid  = threadIdx.x;
    int warp = tid >> 5, lane = tid & 31;
    int gID  = lane >> 2, tig = lane & 3;
    int bh   = blockIdx.y;
    int b    = bh >> 3, h = bh & 7;
    int row0 = blockIdx.x * 64;

    const float* qb = g_q + (size_t)bh * NSEQ * EDIM;
    const float* kb = g_k + (size_t)bh * NSEQ * EDIM;
    const float* vb = g_v + (size_t)bh * NSEQ * EDIM;

    // load Q tile (tf32-rounded)
    for (int l = tid; l < 64 * 48; l += 128) {
        int r = l / 48, e4 = l % 48;
        float4 v = *(const float4*)(qb + (size_t)(row0 + r) * EDIM + e4 * 4);
        float* d = Qs + r * ESTR + e4 * 4;
        d[0] = __uint_as_float(f2tf32(v.x));
        d[1] = __uint_as_float(f2tf32(v.y));
        d[2] = __uint_as_float(f2tf32(v.z));
        d[3] = __uint_as_float(f2tf32(v.w));
    }

    float o[24][4];
#pragma unroll
    for (int nt = 0; nt < 24; nt++)
#pragma unroll
        for (int i = 0; i < 4; i++) o[nt][i] = 0.f;
    float m0r = -1e30f, m1r = -1e30f, l0r = 0.f, l1r = 0.f;

    int m0 = warp * 16;
    float* Pw = Ps + warp * 16 * PSTR;
    const float scale = 0.07216878365f;   // 1/sqrt(192)

    for (int kt0 = 0; kt0 < NSEQ / 32; kt0++) {
        __syncthreads();
        const float* kbt = kb + (size_t)kt0 * 32 * EDIM;
        const float* vbt = vb + (size_t)kt0 * 32 * EDIM;
        for (int l = tid; l < 32 * 48; l += 128) {
            int r = l / 48, e4 = l % 48;
            float4 kv = *(const float4*)(kbt + r * EDIM + e4 * 4);
            float4 vv = *(const float4*)(vbt + r * EDIM + e4 * 4);
            float* dk = Ks + r * ESTR + e4 * 4;
            float* dv = Vs + r * ESTR + e4 * 4;
            dk[0] = __uint_as_float(f2tf32(kv.x)); dk[1] = __uint_as_float(f2tf32(kv.y));
            dk[2] = __uint_as_float(f2tf32(kv.z)); dk[3] = __uint_as_float(f2tf32(kv.w));
            dv[0] = __uint_as_float(f2tf32(vv.x)); dv[1] = __uint_as_float(f2tf32(vv.y));
            dv[2] = __uint_as_float(f2tf32(vv.z)); dv[3] = __uint_as_float(f2tf32(vv.w));
        }
        __syncthreads();

        // ---- S = Q K^T : per warp 16 x 32 (4 n-tiles) ----
        float s[4][4];
#pragma unroll
        for (int nt = 0; nt < 4; nt++)
#pragma unroll
            for (int i = 0; i < 4; i++) s[nt][i] = 0.f;

#pragma unroll 8
        for (int k = 0; k < 24; k++) {
            unsigned a[4];
            a[0] = __float_as_uint(Qs[(m0 + gID)     * ESTR + 8 * k + tig]);
            a[1] = __float_as_uint(Qs[(m0 + gID + 8) * ESTR + 8 * k + tig]);
            a[2] = __float_as_uint(Qs[(m0 + gID)     * ESTR + 8 * k + tig + 4]);
            a[3] = __float_as_uint(Qs[(m0 + gID + 8) * ESTR + 8 * k + tig + 4]);
#pragma unroll
            for (int nt = 0; nt < 4; nt++) {
                unsigned bf[2];
                bf[0] = __float_as_uint(Ks[(8 * nt + gID) * ESTR + 8 * k + tig]);
                bf[1] = __float_as_uint(Ks[(8 * nt + gID) * ESTR + 8 * k + tig + 4]);
                mma_tf32(s[nt], a, bf);
            }
        }

        // ---- online softmax (rows m0+gID and m0+gID+8) ----
        float mx0 = -1e30f, mx1 = -1e30f;
#pragma unroll
        for (int nt = 0; nt < 4; nt++) {
#pragma unroll
            for (int i = 0; i < 4; i++) s[nt][i] *= scale;
            mx0 = fmaxf(mx0, fmaxf(s[nt][0], s[nt][1]));
            mx1 = fmaxf(mx1, fmaxf(s[nt][2], s[nt][3]));
        }
        mx0 = fmaxf(mx0, __shfl_xor_sync(0xffffffffu, mx0, 1));
        mx0 = fmaxf(mx0, __shfl_xor_sync(0xffffffffu, mx0, 2));
        mx1 = fmaxf(mx1, __shfl_xor_sync(0xffffffffu, mx1, 1));
        mx1 = fmaxf(mx1, __shfl_xor_sync(0xffffffffu, mx1, 2));
        float mn0 = fmaxf(m0r, mx0), mn1 = fmaxf(m1r, mx1);
        float c0 = __expf(m0r - mn0), c1 = __expf(m1r - mn1);
        m0r = mn0; m1r = mn1;
        float rs0 = 0.f, rs1 = 0.f;
#pragma unroll
        for (int nt = 0; nt < 4; nt++) {
            s[nt][0] = __expf(s[nt][0] - mn0);
            s[nt][1] = __expf(s[nt][1] - mn0);
            s[nt][2] = __expf(s[nt][2] - mn1);
            s[nt][3] = __expf(s[nt][3] - mn1);
            rs0 += s[nt][0] + s[nt][1];
            rs1 += s[nt][2] + s[nt][3];
        }
        rs0 += __shfl_xor_sync(0xffffffffu, rs0, 1);
        rs0 += __shfl_xor_sync(0xffffffffu, rs0, 2);
        rs1 += __shfl_xor_sync(0xffffffffu, rs1, 1);
        rs1 += __shfl_xor_sync(0xffffffffu, rs1, 2);
        l0r = l0r * c0 + rs0;
        l1r = l1r * c1 + rs1;

#pragma unroll
        for (int nt = 0; nt < 24; nt++) {
            o[nt][0] *= c0; o[nt][1] *= c0;
            o[nt][2] *= c1; o[nt][3] *= c1;
        }

        // stage P (tf32) to per-warp smem
#pragma unroll
        for (int nt = 0; nt < 4; nt++) {
            float2 p0, p1;
            p0.x = __uint_as_float(f2tf32(s[nt][0]));
            p0.y = __uint_as_float(f2tf32(s[nt][1]));
            p1.x = __uint_as_float(f2tf32(s[nt][2]));
            p1.y = __uint_as_float(f2tf32(s[nt][3]));
            *(float2*)(Pw + gID       * PSTR + 8 * nt + 2 * tig) = p0;
            *(float2*)(Pw + (gID + 8) * PSTR + 8 * nt + 2 * tig) = p1;
        }
        __syncwarp();

        // ---- O += P V : 24 n-tiles over E ----
#pragma unroll
        for (int kt = 0; kt < 4; kt++) {
            unsigned a[4];
            a[0] = __float_as_uint(Pw[gID       * PSTR + 8 * kt + tig]);
            a[1] = __float_as_uint(Pw[(gID + 8) * PSTR + 8 * kt + tig]);
            a[2] = __float_as_uint(Pw[gID       * PSTR + 8 * kt + tig + 4]);
            a[3] = __float_as_uint(Pw[(gID + 8) * PSTR + 8 * kt + tig + 4]);
#pragma unroll
            for (int nt = 0; nt < 24; nt++) {
                unsigned bf[2];
                bf[0] = __float_as_uint(Vs[(8 * kt + tig)     * ESTR + 8 * nt + gID]);
                bf[1] = __float_as_uint(Vs[(8 * kt + tig + 4) * ESTR + 8 * nt + gID]);
                mma_tf32(o[nt], a, bf);
            }
        }
    }

    // epilogue: normalize + scatter to merged-head layout g_ao[b][n][h*64+d][c]
    float inv0 = 1.f / l0r, inv1 = 1.f / l1r;
    int n0 = row0 + m0 + gID;
    int n1 = n0 + 8;
#pragma unroll
    for (int nt = 0; nt < 24; nt++) {
#pragma unroll
        for (int half = 0; half < 2; half++) {
            int e = 8 * nt + 2 * tig + half;
            int d = e / 3, cc = e - d * 3;
            size_t i0 = (((size_t)b * NSEQ + n0) * DINNER + h * DHEAD + d) * 3 + cc;
            size_t i1 = (((size_t)b * NSEQ + n1) * DINNER + h * DHEAD + d) * 3 + cc;
            g_ao[i0] = o[nt][half]     * inv0;
            g_ao[i1] = o[nt][2 + half] * inv1;
        }
    }
}

// ---------------------------------------------------------------------------
// Kernel 3: output projection (bank-conflict-fixed X tile)
// grid: (B*N/32, CIN/64), block 256
// ---------------------------------------------------------------------------
__global__ __launch_bounds__(256) void oproj_kernel(
    const float* __restrict__ Wo, float* __restrict__ out)
{
    __shared__ float Xs[32 * XSTR];
    __shared__ float Ws[64][33];

    int row0 = blockIdx.x * 32;
    int o0   = blockIdx.y * 64;
    int tid  = threadIdx.x;
    int ty   = tid >> 4, tx = tid & 15;

    float acc[2][4][3];
#pragma unroll
    for (int i = 0; i < 2; i++)
#pragma unroll
        for (int j = 0; j < 4; j++)
#pragma unroll
            for (int c = 0; c < 3; c++) acc[i][j][c] = 0.f;

    for (int k0 = 0; k0 < DINNER; k0 += 32) {
        __syncthreads();
#pragma unroll
        for (int l = tid; l < 32 * 96; l += 256) {
            int r = l / 96, kc = l % 96;
            Xs[r * XSTR + kc] = g_ao[(size_t)(row0 + r) * (DINNER * COOR) + k0 * COOR + kc];
        }
#pragma unroll
        for (int l = tid; l < 64 * 32; l += 256) {
            int o = l >> 5, k = l & 31;
            Ws[o][k] = Wo[(size_t)(o0 + o) * DINNER + k0 + k];
        }
        __syncthreads();

#pragma unroll 8
        for (int k = 0; k < 32; k++) {
            float xv[2][3], wv[4];
#pragma unroll
            for (int i = 0; i < 2; i++) {
                xv[i][0] = Xs[(2 * ty + i) * XSTR + k * 3 + 0];
                xv[i][1] = Xs[(2 * ty + i) * XSTR + k * 3 + 1];
                xv[i][2] = Xs[(2 * ty + i) * XSTR + k * 3 + 2];
            }
#pragma unroll
            for (int j = 0; j < 4; j++) wv[j] = Ws[tx + 16 * j][k];
#pragma unroll
            for (int i = 0; i < 2; i++)
#pragma unroll
                for (int j = 0; j < 4; j++)
#pragma unroll
                    for (int c = 0; c < 3; c++)
                        acc[i][j][c] += xv[i][c] * wv[j];
        }
    }

#pragma unroll
    for (int i = 0; i < 2; i++) {
        int row = row0 + 2 * ty + i;
#pragma unroll
        for (int j = 0; j < 4; j++) {
            int o = o0 + tx + 16 * j;
#pragma unroll
            for (int c = 0; c < 3; c++)
                out[(size_t)row * (CIN * COOR) + o * 3 + c] = acc[i][j][c];
        }
    }
}

// ---------------------------------------------------------------------------
extern "C" void kernel_launch(void* const* d_in, const int* in_sizes, int n_in,
                              void* d_out, int out_size)
{
    const float* x  = (const float*)d_in[0];
    const float* Wq = (const float*)d_in[1];
    const float* Wk = (const float*)d_in[2];
    const float* Wv = (const float*)d_in[3];
    const float* Wo = (const float*)d_in[4];
    float* out = (float*)d_out;

    const int attn_smem = (64 * ESTR + 2 * 32 * ESTR + 4 * 16 * PSTR) * 4;  // 109568
    cudaFuncSetAttribute(attn_mma_kernel,
                         cudaFuncAttributeMaxDynamicSharedMemorySize, attn_smem);

    qkv_kernel<<<dim3(BDIM * NSEQ / 32, DINNER / 64, 3), 256>>>(x, Wq, Wk, Wv);
    attn_mma_kernel<<<dim3(NSEQ / 64, BDIM * HEADS), 128, attn_smem>>>();
    oproj_kernel<<<dim3(BDIM * NSEQ / 32, CIN / 64), 256>>>(Wo, out);
}

// round 5
// speedup vs baseline: 2.6054x; 1.1328x over previous
#include <cuda_runtime.h>
#include <math.h>
#include <stdint.h>

#define BDIM   2
#define NSEQ   2048
#define CIN    256
#define COOR   3
#define HEADS  8
#define DHEAD  64
#define DINNER 512
#define EDIM   192

// attention tiling
#define KSTR   196   // K/Q smem stride (floats): frag loads conflict-free
#define VSTR   200   // V smem stride: PV B-frag conflict-free (8*tig+gID)
#define PSTR   36
#define KVT    32
#define NKT    (NSEQ/KVT)

// projection tiling
#define PJ_AK  36    // A/W smem stride

// Scratch
__device__ float g_q [BDIM*HEADS*NSEQ*EDIM];
__device__ float g_k [BDIM*HEADS*NSEQ*EDIM];
__device__ float g_v [BDIM*HEADS*NSEQ*EDIM];
__device__ float g_ao[BDIM*NSEQ*DINNER*COOR];

__device__ __forceinline__ unsigned f2tf32(float x) {
    unsigned r; asm("cvt.rna.tf32.f32 %0, %1;" : "=r"(r) : "f"(x)); return r;
}

__device__ __forceinline__ void mma_tf32(float* c, const unsigned* a, const unsigned* b) {
    asm volatile(
        "mma.sync.aligned.m16n8k8.row.col.f32.tf32.tf32.f32 "
        "{%0,%1,%2,%3}, {%4,%5,%6,%7}, {%8,%9}, {%0,%1,%2,%3};"
        : "+f"(c[0]), "+f"(c[1]), "+f"(c[2]), "+f"(c[3])
        : "r"(a[0]), "r"(a[1]), "r"(a[2]), "r"(a[3]), "r"(b[0]), "r"(b[1]));
}

// ===========================================================================
// Kernel 1: QKV projection via tf32 mma.  D[r][o] = sum_k A[r][k] W[o][k]
// A[r][k] = x[bn0+r][k][c].  grid (4096/128, 512/64, 9: wsel*3+c), block 256.
// ===========================================================================
__global__ __launch_bounds__(256) void qkv2_kernel(
    const float* __restrict__ x,
    const float* __restrict__ Wq,
    const float* __restrict__ Wk,
    const float* __restrict__ Wv)
{
    extern __shared__ float sm[];
    float* As[2] = { sm, sm + 128 * PJ_AK };
    float* Ws[2] = { sm + 2 * 128 * PJ_AK, sm + 2 * 128 * PJ_AK + 64 * PJ_AK };

    int z    = blockIdx.z;
    int wsel = z / 3, cc = z % 3;
    const float* W    = (wsel == 0) ? Wq : (wsel == 1 ? Wk : Wv);
    float*       outp = (wsel == 0) ? g_q : (wsel == 1 ? g_k : g_v);

    int bn0 = blockIdx.x * 128;
    int o0  = blockIdx.y * 64;
    int tid = threadIdx.x;
    int warp = tid >> 5, lane = tid & 31;
    int gID = lane >> 2, tig = lane & 3;
    int m0  = warp * 16;

    float areg[16], wreg[8];
    float o_acc[8][4];
#pragma unroll
    for (int nt = 0; nt < 8; nt++)
#pragma unroll
        for (int i = 0; i < 4; i++) o_acc[nt][i] = 0.f;

    const int NC = CIN / 32;  // 8 chunks

    // prologue: chunk 0
#pragma unroll
    for (int j = 0; j < 16; j++) {
        int l = tid + j * 256, r = l >> 5, k = l & 31;
        areg[j] = x[((size_t)(bn0 + r) * CIN + k) * 3 + cc];
    }
#pragma unroll
    for (int j = 0; j < 8; j++) {
        int l = tid + j * 256, o = l >> 5, k = l & 31;
        wreg[j] = W[(size_t)(o0 + o) * CIN + k];
    }
#pragma unroll
    for (int j = 0; j < 16; j++) {
        int l = tid + j * 256, r = l >> 5, k = l & 31;
        As[0][r * PJ_AK + k] = __uint_as_float(f2tf32(areg[j]));
    }
#pragma unroll
    for (int j = 0; j < 8; j++) {
        int l = tid + j * 256, o = l >> 5, k = l & 31;
        Ws[0][o * PJ_AK + k] = __uint_as_float(f2tf32(wreg[j]));
    }
    __syncthreads();

    for (int kc = 0; kc < NC; kc++) {
        int cur = kc & 1;
        if (kc + 1 < NC) {
            int k0 = (kc + 1) * 32;
#pragma unroll
            for (int j = 0; j < 16; j++) {
                int l = tid + j * 256, r = l >> 5, k = l & 31;
                areg[j] = x[((size_t)(bn0 + r) * CIN + k0 + k) * 3 + cc];
            }
#pragma unroll
            for (int j = 0; j < 8; j++) {
                int l = tid + j * 256, o = l >> 5, k = l & 31;
                wreg[j] = W[(size_t)(o0 + o) * CIN + k0 + k];
            }
        }

        const float* A = As[cur];
        const float* Wt = Ws[cur];
#pragma unroll
        for (int ks = 0; ks < 4; ks++) {
            unsigned a[4];
            a[0] = __float_as_uint(A[(m0 + gID)     * PJ_AK + 8 * ks + tig]);
            a[1] = __float_as_uint(A[(m0 + gID + 8) * PJ_AK + 8 * ks + tig]);
            a[2] = __float_as_uint(A[(m0 + gID)     * PJ_AK + 8 * ks + tig + 4]);
            a[3] = __float_as_uint(A[(m0 + gID + 8) * PJ_AK + 8 * ks + tig + 4]);
#pragma unroll
            for (int nt = 0; nt < 8; nt++) {
                unsigned bf[2];
                bf[0] = __float_as_uint(Wt[(8 * nt + gID) * PJ_AK + 8 * ks + tig]);
                bf[1] = __float_as_uint(Wt[(8 * nt + gID) * PJ_AK + 8 * ks + tig + 4]);
                mma_tf32(o_acc[nt], a, bf);
            }
        }

        if (kc + 1 < NC) {
            int nb = (kc + 1) & 1;
#pragma unroll
            for (int j = 0; j < 16; j++) {
                int l = tid + j * 256, r = l >> 5, k = l & 31;
                As[nb][r * PJ_AK + k] = __uint_as_float(f2tf32(areg[j]));
            }
#pragma unroll
            for (int j = 0; j < 8; j++) {
                int l = tid + j * 256, o = l >> 5, k = l & 31;
                Ws[nb][o * PJ_AK + k] = __uint_as_float(f2tf32(wreg[j]));
            }
        }
        __syncthreads();
    }

    // epilogue: scatter into split-head layout g[(b*8+h)*2048+n][d*3+c]
#pragma unroll
    for (int i = 0; i < 2; i++) {
        int r = bn0 + m0 + gID + 8 * i;
        int b = r >> 11, n = r & (NSEQ - 1);
#pragma unroll
        for (int nt = 0; nt < 8; nt++) {
#pragma unroll
            for (int half = 0; half < 2; half++) {
                int o = o0 + 8 * nt + 2 * tig + half;
                int h = o >> 6, d = o & 63;
                outp[((size_t)(b * HEADS + h) * NSEQ + n) * EDIM + d * 3 + cc] =
                    o_acc[nt][2 * i + half];
            }
        }
    }
}

// ===========================================================================
// Kernel 2: flash attention, tf32 mma, unnormalized-exp softmax,
// double-buffered K/V (split prefetch).  grid (NSEQ/128, B*H), block 256.
// ===========================================================================
__global__ __launch_bounds__(256, 1) void attn2_kernel()
{
    extern __shared__ float sm[];
    float* Qs    = sm;                               // 128*KSTR
    float* Ksb[2] = { sm + 128 * KSTR, sm + 128 * KSTR + KVT * KSTR };
    float* Vsb[2] = { sm + 128 * KSTR + 2 * KVT * KSTR,
                      sm + 128 * KSTR + 2 * KVT * KSTR + KVT * VSTR };
    float* Ps    = sm + 128 * KSTR + 2 * KVT * KSTR + 2 * KVT * VSTR;  // 8*16*PSTR

    int tid  = threadIdx.x;
    int warp = tid >> 5, lane = tid & 31;
    int gID  = lane >> 2, tig = lane & 3;
    int bh   = blockIdx.y;
    int b    = bh >> 3, h = bh & 7;
    int row0 = blockIdx.x * 128;
    int m0   = warp * 16;

    const float* qb = g_q + (size_t)bh * NSEQ * EDIM;
    const float* kb = g_k + (size_t)bh * NSEQ * EDIM;
    const float* vb = g_v + (size_t)bh * NSEQ * EDIM;

    // load Q tile (tf32-rounded): 128 rows * 48 float4 = 24 per thread
#pragma unroll
    for (int j = 0; j < 24; j++) {
        int l = tid + j * 256;
        int r = l / 48, e4 = l % 48;
        float4 v = *(const float4*)(qb + (size_t)(row0 + r) * EDIM + e4 * 4);
        float* d = Qs + r * KSTR + e4 * 4;
        d[0] = __uint_as_float(f2tf32(v.x)); d[1] = __uint_as_float(f2tf32(v.y));
        d[2] = __uint_as_float(f2tf32(v.z)); d[3] = __uint_as_float(f2tf32(v.w));
    }

    float o_acc[24][4];
#pragma unroll
    for (int nt = 0; nt < 24; nt++)
#pragma unroll
        for (int i = 0; i < 4; i++) o_acc[nt][i] = 0.f;
    float lsum0 = 0.f, lsum1 = 0.f;

    const float scale = 0.07216878364870322f;  // 1/sqrt(192)
    float* Pw = Ps + warp * 16 * PSTR;

    // prologue: tile 0 -> buf 0 (KVT=32 rows * 48 float4 = 1536 = 6 per thread)
    {
        float4 kreg[6], vreg[6];
#pragma unroll
        for (int j = 0; j < 6; j++) {
            int l = tid + j * 256;
            int r = l / 48, e4 = l % 48;
            kreg[j] = *(const float4*)(kb + (size_t)r * EDIM + e4 * 4);
            vreg[j] = *(const float4*)(vb + (size_t)r * EDIM + e4 * 4);
        }
#pragma unroll
        for (int j = 0; j < 6; j++) {
            int l = tid + j * 256;
            int r = l / 48, e4 = l % 48;
            float* dk = Ksb[0] + r * KSTR + e4 * 4;
            float* dv = Vsb[0] + r * VSTR + e4 * 4;
            dk[0] = __uint_as_float(f2tf32(kreg[j].x)); dk[1] = __uint_as_float(f2tf32(kreg[j].y));
            dk[2] = __uint_as_float(f2tf32(kreg[j].z)); dk[3] = __uint_as_float(f2tf32(kreg[j].w));
            dv[0] = __uint_as_float(f2tf32(vreg[j].x)); dv[1] = __uint_as_float(f2tf32(vreg[j].y));
            dv[2] = __uint_as_float(f2tf32(vreg[j].z)); dv[3] = __uint_as_float(f2tf32(vreg[j].w));
        }
    }
    __syncthreads();

    for (int t = 0; t < NKT; t++) {
        int cur = t & 1;
        int nb  = cur ^ 1;
        bool more = (t + 1 < NKT);
        const float* kbt = kb + (size_t)(t + 1) * KVT * EDIM;
        const float* vbt = vb + (size_t)(t + 1) * KVT * EDIM;

        // --- prefetch next K into regs ---
        float4 kreg[6];
        if (more) {
#pragma unroll
            for (int j = 0; j < 6; j++) {
                int l = tid + j * 256;
                int r = l / 48, e4 = l % 48;
                kreg[j] = *(const float4*)(kbt + (size_t)r * EDIM + e4 * 4);
            }
        }

        const float* Ks = Ksb[cur];
        const float* Vs = Vsb[cur];

        // ---- S = Q K^T : per warp 16 x 32 ----
        float s[4][4];
#pragma unroll
        for (int nt = 0; nt < 4; nt++)
#pragma unroll
            for (int i = 0; i < 4; i++) s[nt][i] = 0.f;

#pragma unroll
        for (int ks = 0; ks < 24; ks++) {
            unsigned a[4];
            a[0] = __float_as_uint(Qs[(m0 + gID)     * KSTR + 8 * ks + tig]);
            a[1] = __float_as_uint(Qs[(m0 + gID + 8) * KSTR + 8 * ks + tig]);
            a[2] = __float_as_uint(Qs[(m0 + gID)     * KSTR + 8 * ks + tig + 4]);
            a[3] = __float_as_uint(Qs[(m0 + gID + 8) * KSTR + 8 * ks + tig + 4]);
#pragma unroll
            for (int nt = 0; nt < 4; nt++) {
                unsigned bf[2];
                bf[0] = __float_as_uint(Ks[(8 * nt + gID) * KSTR + 8 * ks + tig]);
                bf[1] = __float_as_uint(Ks[(8 * nt + gID) * KSTR + 8 * ks + tig + 4]);
                mma_tf32(s[nt], a, bf);
            }
        }

        // store next K to the other buffer
        if (more) {
#pragma unroll
            for (int j = 0; j < 6; j++) {
                int l = tid + j * 256;
                int r = l / 48, e4 = l % 48;
                float* dk = Ksb[nb] + r * KSTR + e4 * 4;
                dk[0] = __uint_as_float(f2tf32(kreg[j].x)); dk[1] = __uint_as_float(f2tf32(kreg[j].y));
                dk[2] = __uint_as_float(f2tf32(kreg[j].z)); dk[3] = __uint_as_float(f2tf32(kreg[j].w));
            }
        }

        // ---- unnormalized exp + P staging ----
#pragma unroll
        for (int nt = 0; nt < 4; nt++) {
            float p0 = __expf(s[nt][0] * scale);
            float p1 = __expf(s[nt][1] * scale);
            float p2 = __expf(s[nt][2] * scale);
            float p3 = __expf(s[nt][3] * scale);
            lsum0 += p0 + p1;
            lsum1 += p2 + p3;
            float2 w0, w1;
            w0.x = __uint_as_float(f2tf32(p0)); w0.y = __uint_as_float(f2tf32(p1));
            w1.x = __uint_as_float(f2tf32(p2)); w1.y = __uint_as_float(f2tf32(p3));
            *(float2*)(Pw + gID       * PSTR + 8 * nt + 2 * tig) = w0;
            *(float2*)(Pw + (gID + 8) * PSTR + 8 * nt + 2 * tig) = w1;
        }
        __syncwarp();

        // --- prefetch next V into regs ---
        float4 vreg[6];
        if (more) {
#pragma unroll
            for (int j = 0; j < 6; j++) {
                int l = tid + j * 256;
                int r = l / 48, e4 = l % 48;
                vreg[j] = *(const float4*)(vbt + (size_t)r * EDIM + e4 * 4);
            }
        }

        // ---- O += P V ----
#pragma unroll
        for (int kt = 0; kt < 4; kt++) {
            unsigned a[4];
            a[0] = __float_as_uint(Pw[gID       * PSTR + 8 * kt + tig]);
            a[1] = __float_as_uint(Pw[(gID + 8) * PSTR + 8 * kt + tig]);
            a[2] = __float_as_uint(Pw[gID       * PSTR + 8 * kt + tig + 4]);
            a[3] = __float_as_uint(Pw[(gID + 8) * PSTR + 8 * kt + tig + 4]);
#pragma unroll
            for (int nt = 0; nt < 24; nt++) {
                unsigned bf[2];
                bf[0] = __float_as_uint(Vs[(8 * kt + tig)     * VSTR + 8 * nt + gID]);
                bf[1] = __float_as_uint(Vs[(8 * kt + tig + 4) * VSTR + 8 * nt + gID]);
                mma_tf32(o_acc[nt], a, bf);
            }
        }

        if (more) {
#pragma unroll
            for (int j = 0; j < 6; j++) {
                int l = tid + j * 256;
                int r = l / 48, e4 = l % 48;
                float* dv = Vsb[nb] + r * VSTR + e4 * 4;
                dv[0] = __uint_as_float(f2tf32(vreg[j].x)); dv[1] = __uint_as_float(f2tf32(vreg[j].y));
                dv[2] = __uint_as_float(f2tf32(vreg[j].z)); dv[3] = __uint_as_float(f2tf32(vreg[j].w));
            }
        }
        __syncthreads();
    }

    // reduce row sums across the 4 tig lanes
    lsum0 += __shfl_xor_sync(0xffffffffu, lsum0, 1);
    lsum0 += __shfl_xor_sync(0xffffffffu, lsum0, 2);
    lsum1 += __shfl_xor_sync(0xffffffffu, lsum1, 1);
    lsum1 += __shfl_xor_sync(0xffffffffu, lsum1, 2);
    float inv0 = 1.f / lsum0, inv1 = 1.f / lsum1;

    int n0 = row0 + m0 + gID;
    int n1 = n0 + 8;
    float* d0 = g_ao + ((size_t)b * NSEQ + n0) * (DINNER * COOR) + h * EDIM;
    float* d1 = g_ao + ((size_t)b * NSEQ + n1) * (DINNER * COOR) + h * EDIM;
#pragma unroll
    for (int nt = 0; nt < 24; nt++) {
#pragma unroll
        for (int half = 0; half < 2; half++) {
            int e = 8 * nt + 2 * tig + half;
            d0[e] = o_acc[nt][half]     * inv0;
            d1[e] = o_acc[nt][2 + half] * inv1;
        }
    }
}

// ===========================================================================
// Kernel 3: output projection via tf32 mma.  K=512, N=256.
// grid (4096/128, 256/64, 3: c), block 256.
// ===========================================================================
__global__ __launch_bounds__(256) void oproj2_kernel(
    const float* __restrict__ Wo, float* __restrict__ out)
{
    extern __shared__ float sm[];
    float* As[2] = { sm, sm + 128 * PJ_AK };
    float* Ws[2] = { sm + 2 * 128 * PJ_AK, sm + 2 * 128 * PJ_AK + 64 * PJ_AK };

    int cc  = blockIdx.z;
    int bn0 = blockIdx.x * 128;
    int o0  = blockIdx.y * 64;
    int tid = threadIdx.x;
    int warp = tid >> 5, lane = tid & 31;
    int gID = lane >> 2, tig = lane & 3;
    int m0  = warp * 16;

    float areg[16], wreg[8];
    float o_acc[8][4];
#pragma unroll
    for (int nt = 0; nt < 8; nt++)
#pragma unroll
        for (int i = 0; i < 4; i++) o_acc[nt][i] = 0.f;

    const int NC = DINNER / 32;  // 16

#pragma unroll
    for (int j = 0; j < 16; j++) {
        int l = tid + j * 256, r = l >> 5, k = l & 31;
        areg[j] = g_ao[((size_t)(bn0 + r) * DINNER + k) * 3 + cc];
    }
#pragma unroll
    for (int j = 0; j < 8; j++) {
        int l = tid + j * 256, o = l >> 5, k = l & 31;
        wreg[j] = Wo[(size_t)(o0 + o) * DINNER + k];
    }
#pragma unroll
    for (int j = 0; j < 16; j++) {
        int l = tid + j * 256, r = l >> 5, k = l & 31;
        As[0][r * PJ_AK + k] = __uint_as_float(f2tf32(areg[j]));
    }
#pragma unroll
    for (int j = 0; j < 8; j++) {
        int l = tid + j * 256, o = l >> 5, k = l & 31;
        Ws[0][o * PJ_AK + k] = __uint_as_float(f2tf32(wreg[j]));
    }
    __syncthreads();

    for (int kc = 0; kc < NC; kc++) {
        int cur = kc & 1;
        if (kc + 1 < NC) {
            int k0 = (kc + 1) * 32;
#pragma unroll
            for (int j = 0; j < 16; j++) {
                int l = tid + j * 256, r = l >> 5, k = l & 31;
                areg[j] = g_ao[((size_t)(bn0 + r) * DINNER + k0 + k) * 3 + cc];
            }
#pragma unroll
            for (int j = 0; j < 8; j++) {
                int l = tid + j * 256, o = l >> 5, k = l & 31;
                wreg[j] = Wo[(size_t)(o0 + o) * DINNER + k0 + k];
            }
        }

        const float* A = As[cur];
        const float* Wt = Ws[cur];
#pragma unroll
        for (int ks = 0; ks < 4; ks++) {
            unsigned a[4];
            a[0] = __float_as_uint(A[(m0 + gID)     * PJ_AK + 8 * ks + tig]);
            a[1] = __float_as_uint(A[(m0 + gID + 8) * PJ_AK + 8 * ks + tig]);
            a[2] = __float_as_uint(A[(m0 + gID)     * PJ_AK + 8 * ks + tig + 4]);
            a[3] = __float_as_uint(A[(m0 + gID + 8) * PJ_AK + 8 * ks + tig + 4]);
#pragma unroll
            for (int nt = 0; nt < 8; nt++) {
                unsigned bf[2];
                bf[0] = __float_as_uint(Wt[(8 * nt + gID) * PJ_AK + 8 * ks + tig]);
                bf[1] = __float_as_uint(Wt[(8 * nt + gID) * PJ_AK + 8 * ks + tig + 4]);
                mma_tf32(o_acc[nt], a, bf);
            }
        }

        if (kc + 1 < NC) {
            int nb = (kc + 1) & 1;
#pragma unroll
            for (int j = 0; j < 16; j++) {
                int l = tid + j * 256, r = l >> 5, k = l & 31;
                As[nb][r * PJ_AK + k] = __uint_as_float(f2tf32(areg[j]));
            }
#pragma unroll
            for (int j = 0; j < 8; j++) {
                int l = tid + j * 256, o = l >> 5, k = l & 31;
                Ws[nb][o * PJ_AK + k] = __uint_as_float(f2tf32(wreg[j]));
            }
        }
        __syncthreads();
    }

#pragma unroll
    for (int i = 0; i < 2; i++) {
        int r = bn0 + m0 + gID + 8 * i;
#pragma unroll
        for (int nt = 0; nt < 8; nt++) {
#pragma unroll
            for (int half = 0; half < 2; half++) {
                int o = o0 + 8 * nt + 2 * tig + half;
                out[((size_t)r * CIN + o) * 3 + cc] = o_acc[nt][2 * i + half];
            }
        }
    }
}

// ---------------------------------------------------------------------------
extern "C" void kernel_launch(void* const* d_in, const int* in_sizes, int n_in,
                              void* d_out, int out_size)
{
    const float* x  = (const float*)d_in[0];
    const float* Wq = (const float*)d_in[1];
    const float* Wk = (const float*)d_in[2];
    const float* Wv = (const float*)d_in[3];
    const float* Wo = (const float*)d_in[4];
    float* out = (float*)d_out;

    const int pj_smem   = (2 * 128 * PJ_AK + 2 * 64 * PJ_AK) * 4;          // 55296
    const int attn_smem = (128 * KSTR + 2 * KVT * KSTR + 2 * KVT * VSTR
                           + 8 * 16 * PSTR) * 4;                            // 220160

    cudaFuncSetAttribute(qkv2_kernel,
                         cudaFuncAttributeMaxDynamicSharedMemorySize, pj_smem);
    cudaFuncSetAttribute(attn2_kernel,
                         cudaFuncAttributeMaxDynamicSharedMemorySize, attn_smem);
    cudaFuncSetAttribute(oproj2_kernel,
                         cudaFuncAttributeMaxDynamicSharedMemorySize, pj_smem);

    qkv2_kernel<<<dim3(BDIM * NSEQ / 128, DINNER / 64, 9), 256, pj_smem>>>(x, Wq, Wk, Wv);
    attn2_kernel<<<dim3(NSEQ / 128, BDIM * HEADS), 256, attn_smem>>>();
    oproj2_kernel<<<dim3(BDIM * NSEQ / 128, CIN / 64, 3), 256, pj_smem>>>(Wo, out);
}

// round 8
// speedup vs baseline: 3.6189x; 1.3890x over previous
#include <cuda_runtime.h>
#include <cuda_fp16.h>
#include <math.h>
#include <stdint.h>

#define BDIM   2
#define NSEQ   2048
#define CIN    256
#define COOR   3
#define HEADS  8
#define DHEAD  64
#define DINNER 512
#define EDIM   192

// attention tiling (halves)
#define QSTRH  200   // Q/K smem row stride: 400B -> 4-bank row step, conflict-free frags
#define VSTRH  36    // Vt row stride: 72B -> 18-bank step, conflict-free
#define PSTRH  40    // P row stride: 80B -> 20-bank step, conflict-free
#define KVT    32
#define NKT    (NSEQ/KVT)

// projection tiling
#define AKH    40    // A/W smem stride (halves): 80B -> 20-bank step

// Scratch (fp16)
__device__ __half g_q [BDIM*HEADS*NSEQ*EDIM];
__device__ __half g_k [BDIM*HEADS*NSEQ*EDIM];
__device__ __half g_v [BDIM*HEADS*NSEQ*EDIM];
__device__ __half g_ao[BDIM*NSEQ*DINNER*COOR];

__device__ __forceinline__ void mma_f16(float* c, const unsigned* a, const unsigned* b) {
    asm volatile(
        "mma.sync.aligned.m16n8k16.row.col.f32.f16.f16.f32 "
        "{%0,%1,%2,%3}, {%4,%5,%6,%7}, {%8,%9}, {%0,%1,%2,%3};"
        : "+f"(c[0]), "+f"(c[1]), "+f"(c[2]), "+f"(c[3])
        : "r"(a[0]), "r"(a[1]), "r"(a[2]), "r"(a[3]), "r"(b[0]), "r"(b[1]));
}

__device__ __forceinline__ uint32_t smem_u32(const void* p) {
    uint32_t a;
    asm("{ .reg .u64 t; cvta.to.shared.u64 t, %1; cvt.u32.u64 %0, t; }"
        : "=r"(a) : "l"(p));
    return a;
}
__device__ __forceinline__ void cp16(uint32_t dst, const void* src) {
    asm volatile("cp.async.ca.shared.global [%0], [%1], 16;" :: "r"(dst), "l"(src));
}
#define CP_COMMIT() asm volatile("cp.async.commit_group;" ::: "memory")
#define CP_WAIT0()  asm volatile("cp.async.wait_group 0;" ::: "memory")

// ===========================================================================
// Kernel 1: QKV projection, fp16 mma.  Block: 64 bn-rows x 3 coords x 64 out.
// M = 192 A-rows (c*64 + bnl).  grid (BN/64, DINNER/64, 3), block 384 (12 warps).
// ===========================================================================
__global__ __launch_bounds__(384, 1) void qkv3_kernel(
    const float* __restrict__ x,
    const float* __restrict__ Wq,
    const float* __restrict__ Wk,
    const float* __restrict__ Wv)
{
    extern __shared__ __half smh[];
    __half* As[2] = { smh, smh + 192 * AKH };
    __half* Ws[2] = { smh + 2 * 192 * AKH, smh + 2 * 192 * AKH + 64 * AKH };

    int wsel = blockIdx.z;
    const float* W    = (wsel == 0) ? Wq : (wsel == 1 ? Wk : Wv);
    __half*      outp = (wsel == 0) ? g_q : (wsel == 1 ? g_k : g_v);

    int bn0 = blockIdx.x * 64;
    int o0  = blockIdx.y * 64;
    int tid = threadIdx.x;
    int warp = tid >> 5, lane = tid & 31;
    int gID = lane >> 2, tig = lane & 3;
    int m0  = warp * 16;

    float o_acc[8][4];
#pragma unroll
    for (int nt = 0; nt < 8; nt++)
#pragma unroll
        for (int i = 0; i < 4; i++) o_acc[nt][i] = 0.f;

    const int NC = CIN / 32;  // 8 chunks
    float4 areg[4];  // 64 rows * 24 float4 = 1536 /384 = 4
    float  wreg[6];  // 64*32 = 2048 /384 = 5.33

    // prologue: chunk 0 -> buf 0
#pragma unroll
    for (int j = 0; j < 4; j++) {
        int l = tid + j * 384, r = l / 24, q4 = l % 24;
        areg[j] = *(const float4*)(x + (size_t)(bn0 + r) * (CIN * COOR) + q4 * 4);
    }
#pragma unroll
    for (int j = 0; j < 6; j++) {
        int l = tid + j * 384;
        if (l < 2048) { int o = l >> 5, k = l & 31; wreg[j] = W[(size_t)(o0 + o) * CIN + k]; }
    }
#pragma unroll
    for (int j = 0; j < 4; j++) {
        int l = tid + j * 384, r = l / 24, q4 = l % 24;
        float f[4] = { areg[j].x, areg[j].y, areg[j].z, areg[j].w };
#pragma unroll
        for (int m = 0; m < 4; m++) {
            int p = q4 * 4 + m, k = p / 3, c = p - 3 * k;
            As[0][(c * 64 + r) * AKH + k] = __float2half(f[m]);
        }
    }
#pragma unroll
    for (int j = 0; j < 6; j++) {
        int l = tid + j * 384;
        if (l < 2048) { int o = l >> 5, k = l & 31; Ws[0][o * AKH + k] = __float2half(wreg[j]); }
    }
    __syncthreads();

    for (int kc = 0; kc < NC; kc++) {
        int cur = kc & 1, nb = cur ^ 1;
        bool more = (kc + 1 < NC);
        if (more) {
            int k0 = (kc + 1) * 32;
#pragma unroll
            for (int j = 0; j < 4; j++) {
                int l = tid + j * 384, r = l / 24, q4 = l % 24;
                areg[j] = *(const float4*)(x + (size_t)(bn0 + r) * (CIN * COOR) + k0 * 3 + q4 * 4);
            }
#pragma unroll
            for (int j = 0; j < 6; j++) {
                int l = tid + j * 384;
                if (l < 2048) { int o = l >> 5, k = l & 31; wreg[j] = W[(size_t)(o0 + o) * CIN + k0 + k]; }
            }
        }

        const __half* A  = As[cur];
        const __half* Wt = Ws[cur];
#pragma unroll
        for (int ks = 0; ks < 2; ks++) {
            unsigned a[4];
            a[0] = *(const unsigned*)(A + (m0 + gID)     * AKH + 16 * ks + 2 * tig);
            a[1] = *(const unsigned*)(A + (m0 + gID + 8) * AKH + 16 * ks + 2 * tig);
            a[2] = *(const unsigned*)(A + (m0 + gID)     * AKH + 16 * ks + 2 * tig + 8);
            a[3] = *(const unsigned*)(A + (m0 + gID + 8) * AKH + 16 * ks + 2 * tig + 8);
#pragma unroll
            for (int nt = 0; nt < 8; nt++) {
                unsigned bf[2];
                bf[0] = *(const unsigned*)(Wt + (8 * nt + gID) * AKH + 16 * ks + 2 * tig);
                bf[1] = *(const unsigned*)(Wt + (8 * nt + gID) * AKH + 16 * ks + 2 * tig + 8);
                mma_f16(o_acc[nt], a, bf);
            }
        }

        if (more) {
#pragma unroll
            for (int j = 0; j < 4; j++) {
                int l = tid + j * 384, r = l / 24, q4 = l % 24;
                float f[4] = { areg[j].x, areg[j].y, areg[j].z, areg[j].w };
#pragma unroll
                for (int m = 0; m < 4; m++) {
                    int p = q4 * 4 + m, k = p / 3, c = p - 3 * k;
                    As[nb][(c * 64 + r) * AKH + k] = __float2half(f[m]);
                }
            }
#pragma unroll
            for (int j = 0; j < 6; j++) {
                int l = tid + j * 384;
                if (l < 2048) { int o = l >> 5, k = l & 31; Ws[nb][o * AKH + k] = __float2half(wreg[j]); }
            }
        }
        __syncthreads();
    }

    // epilogue -> split-head fp16: g[(b*8+hh)*2048+n][d*3+c]
#pragma unroll
    for (int i = 0; i < 2; i++) {
        int arow = m0 + gID + 8 * i;          // 0..191
        int c = arow >> 6, bnl = arow & 63;
        int bn = bn0 + bnl;
        int b = bn >> 11, n = bn & (NSEQ - 1);
#pragma unroll
        for (int nt = 0; nt < 8; nt++) {
#pragma unroll
            for (int hh = 0; hh < 2; hh++) {
                int o = o0 + 8 * nt + 2 * tig + hh;
                int hd = o >> 6, d = o & 63;
                outp[((size_t)(b * HEADS + hd) * NSEQ + n) * EDIM + d * 3 + c] =
                    __float2half(o_acc[nt][2 * i + hh]);
            }
        }
    }
}

// ===========================================================================
// Kernel 2: flash attention, fp16 mma, unnormalized-exp softmax,
// cp.async K double-buffer, transposed V.  grid (NSEQ/128, B*H), block 256.
// ===========================================================================
#define SMQ  0
#define SMK  (128*QSTRH)                   // 25600
#define SMV  (SMK + 2*KVT*QSTRH)           // 38400
#define SMP  (SMV + 2*EDIM*VSTRH)          // 52224
#define SMTOT_H (SMP + 8*16*PSTRH)         // 57344 halves = 114688 B

__global__ __launch_bounds__(256, 1) void attn3_kernel()
{
    extern __shared__ __half smh[];
    __half* Qs = smh + SMQ;
    __half* Ks[2] = { smh + SMK, smh + SMK + KVT * QSTRH };
    __half* Vt[2] = { smh + SMV, smh + SMV + EDIM * VSTRH };
    __half* Ps = smh + SMP;

    uint32_t ks_u32[2];
    ks_u32[0] = smem_u32(Ks[0]);
    ks_u32[1] = smem_u32(Ks[1]);

    int tid  = threadIdx.x;
    int warp = tid >> 5, lane = tid & 31;
    int gID  = lane >> 2, tig = lane & 3;
    int bh   = blockIdx.y;
    int b    = bh >> 3, h = bh & 7;
    int row0 = blockIdx.x * 128;
    int m0   = warp * 16;

    const __half* qb = g_q + (size_t)bh * NSEQ * EDIM;
    const __half* kb = g_k + (size_t)bh * NSEQ * EDIM;
    const __half* vb = g_v + (size_t)bh * NSEQ * EDIM;

    // load Q tile: 128 rows x 24 uint4 = 3072 -> 12 per thread
#pragma unroll
    for (int j = 0; j < 12; j++) {
        int l = tid + j * 256, r = l / 24, e8 = l % 24;
        *(uint4*)(Qs + r * QSTRH + e8 * 8) =
            *(const uint4*)(qb + (size_t)(row0 + r) * EDIM + e8 * 8);
    }

    float o_acc[24][4];
#pragma unroll
    for (int nt = 0; nt < 24; nt++)
#pragma unroll
        for (int i = 0; i < 4; i++) o_acc[nt][i] = 0.f;
    float lsum0 = 0.f, lsum1 = 0.f;

    const float scale = 0.07216878364870322f;  // 1/sqrt(192)
    __half* Pw = Ps + warp * 16 * PSTRH;

    // prologue: tile 0
    {
#pragma unroll
        for (int j = 0; j < 3; j++) {  // K: 32 rows * 24 uint4 = 768 -> 3/thread
            int l = tid + j * 256, r = l / 24, e8 = l % 24;
            cp16(ks_u32[0] + (r * QSTRH + e8 * 8) * 2, kb + (size_t)r * EDIM + e8 * 8);
        }
        CP_COMMIT();
#pragma unroll
        for (int j = 0; j < 3; j++) {  // V transpose
            int l = tid + j * 256, r = l / 24, e8 = l % 24;
            uint4 v = *(const uint4*)(vb + (size_t)r * EDIM + e8 * 8);
            const __half* hv = (const __half*)&v;
#pragma unroll
            for (int m = 0; m < 8; m++)
                Vt[0][(e8 * 8 + m) * VSTRH + r] = hv[m];
        }
        CP_WAIT0();
    }
    __syncthreads();

    for (int t = 0; t < NKT; t++) {
        int cur = t & 1, nb = cur ^ 1;
        bool more = (t + 1 < NKT);
        const __half* kbt = kb + (size_t)(t + 1) * KVT * EDIM;
        const __half* vbt = vb + (size_t)(t + 1) * KVT * EDIM;

        uint4 vreg[3];
        if (more) {
#pragma unroll
            for (int j = 0; j < 3; j++) {
                int l = tid + j * 256, r = l / 24, e8 = l % 24;
                cp16(ks_u32[nb] + (r * QSTRH + e8 * 8) * 2, kbt + (size_t)r * EDIM + e8 * 8);
            }
            CP_COMMIT();
#pragma unroll
            for (int j = 0; j < 3; j++) {
                int l = tid + j * 256, r = l / 24, e8 = l % 24;
                vreg[j] = *(const uint4*)(vbt + (size_t)r * EDIM + e8 * 8);
            }
        }

        const __half* Kc = Ks[cur];
        const __half* Vc = Vt[cur];

        // ---- S = Q K^T : 16 x 32 per warp, 12 k16-steps ----
        float s[4][4];
#pragma unroll
        for (int nt = 0; nt < 4; nt++)
#pragma unroll
            for (int i = 0; i < 4; i++) s[nt][i] = 0.f;

#pragma unroll
        for (int ks = 0; ks < 12; ks++) {
            unsigned a[4];
            a[0] = *(const unsigned*)(Qs + (m0 + gID)     * QSTRH + 16 * ks + 2 * tig);
            a[1] = *(const unsigned*)(Qs + (m0 + gID + 8) * QSTRH + 16 * ks + 2 * tig);
            a[2] = *(const unsigned*)(Qs + (m0 + gID)     * QSTRH + 16 * ks + 2 * tig + 8);
            a[3] = *(const unsigned*)(Qs + (m0 + gID + 8) * QSTRH + 16 * ks + 2 * tig + 8);
#pragma unroll
            for (int nt = 0; nt < 4; nt++) {
                unsigned bf[2];
                bf[0] = *(const unsigned*)(Kc + (8 * nt + gID) * QSTRH + 16 * ks + 2 * tig);
                bf[1] = *(const unsigned*)(Kc + (8 * nt + gID) * QSTRH + 16 * ks + 2 * tig + 8);
                mma_f16(s[nt], a, bf);
            }
        }

        // store next V transposed (Vt[nb] free since end of t-1)
        if (more) {
#pragma unroll
            for (int j = 0; j < 3; j++) {
                int l = tid + j * 256, r = l / 24, e8 = l % 24;
                const __half* hv = (const __half*)&vreg[j];
#pragma unroll
                for (int m = 0; m < 8; m++)
                    Vt[nb][(e8 * 8 + m) * VSTRH + r] = hv[m];
            }
        }

        // ---- unnormalized exp + P staging (fp16) ----
#pragma unroll
        for (int nt = 0; nt < 4; nt++) {
            float p0 = __expf(s[nt][0] * scale);
            float p1 = __expf(s[nt][1] * scale);
            float p2 = __expf(s[nt][2] * scale);
            float p3 = __expf(s[nt][3] * scale);
            lsum0 += p0 + p1;
            lsum1 += p2 + p3;
            *(__half2*)(Pw + gID       * PSTRH + 8 * nt + 2 * tig) = __floats2half2_rn(p0, p1);
            *(__half2*)(Pw + (gID + 8) * PSTRH + 8 * nt + 2 * tig) = __floats2half2_rn(p2, p3);
        }
        __syncwarp();

        // ---- O += P V : 2 k16-steps, 24 n-tiles ----
#pragma unroll
        for (int kt = 0; kt < 2; kt++) {
            unsigned a[4];
            a[0] = *(const unsigned*)(Pw + gID       * PSTRH + 16 * kt + 2 * tig);
            a[1] = *(const unsigned*)(Pw + (gID + 8) * PSTRH + 16 * kt + 2 * tig);
            a[2] = *(const unsigned*)(Pw + gID       * PSTRH + 16 * kt + 2 * tig + 8);
            a[3] = *(const unsigned*)(Pw + (gID + 8) * PSTRH + 16 * kt + 2 * tig + 8);
#pragma unroll
            for (int nt = 0; nt < 24; nt++) {
                unsigned bf[2];
                bf[0] = *(const unsigned*)(Vc + (8 * nt + gID) * VSTRH + 16 * kt + 2 * tig);
                bf[1] = *(const unsigned*)(Vc + (8 * nt + gID) * VSTRH + 16 * kt + 2 * tig + 8);
                mma_f16(o_acc[nt], a, bf);
            }
        }

        if (more) CP_WAIT0();
        __syncthreads();
    }

    // reduce row sums across the 4 tig lanes
    lsum0 += __shfl_xor_sync(0xffffffffu, lsum0, 1);
    lsum0 += __shfl_xor_sync(0xffffffffu, lsum0, 2);
    lsum1 += __shfl_xor_sync(0xffffffffu, lsum1, 1);
    lsum1 += __shfl_xor_sync(0xffffffffu, lsum1, 2);
    float inv0 = 1.f / lsum0, inv1 = 1.f / lsum1;

    int n0 = row0 + m0 + gID;
    int n1 = n0 + 8;
    __half* d0 = g_ao + ((size_t)b * NSEQ + n0) * (DINNER * COOR) + h * EDIM;
    __half* d1 = g_ao + ((size_t)b * NSEQ + n1) * (DINNER * COOR) + h * EDIM;
#pragma unroll
    for (int nt = 0; nt < 24; nt++) {
#pragma unroll
        for (int hh = 0; hh < 2; hh++) {
            int e = 8 * nt + 2 * tig + hh;
            d0[e] = __float2half(o_acc[nt][hh]     * inv0);
            d1[e] = __float2half(o_acc[nt][2 + hh] * inv1);
        }
    }
}

// ===========================================================================
// Kernel 3: output projection, fp16 mma.  M=192 (c*64+bnl), K=512, N=64/blk.
// grid (BN/64, CIN/64), block 384 (12 warps).
// ===========================================================================
__global__ __launch_bounds__(384, 1) void oproj3_kernel(
    const float* __restrict__ Wo, float* __restrict__ out)
{
    extern __shared__ __half smh[];
    __half* As[2] = { smh, smh + 192 * AKH };
    __half* Ws[2] = { smh + 2 * 192 * AKH, smh + 2 * 192 * AKH + 64 * AKH };

    int bn0 = blockIdx.x * 64;
    int o0  = blockIdx.y * 64;
    int tid = threadIdx.x;
    int warp = tid >> 5, lane = tid & 31;
    int gID = lane >> 2, tig = lane & 3;
    int m0  = warp * 16;

    float o_acc[8][4];
#pragma unroll
    for (int nt = 0; nt < 8; nt++)
#pragma unroll
        for (int i = 0; i < 4; i++) o_acc[nt][i] = 0.f;

    const int NC = DINNER / 32;  // 16 chunks
    uint4 areg[2];   // 64 rows * 12 uint4 = 768 /384 = 2
    float wreg[6];

    // prologue: chunk 0
#pragma unroll
    for (int j = 0; j < 2; j++) {
        int l = tid + j * 384, r = l / 12, q8 = l % 12;
        areg[j] = *(const uint4*)(g_ao + (size_t)(bn0 + r) * (DINNER * COOR) + q8 * 8);
    }
#pragma unroll
    for (int j = 0; j < 6; j++) {
        int l = tid + j * 384;
        if (l < 2048) { int o = l >> 5, k = l & 31; wreg[j] = Wo[(size_t)(o0 + o) * DINNER + k]; }
    }
#pragma unroll
    for (int j = 0; j < 2; j++) {
        int l = tid + j * 384, r = l / 12, q8 = l % 12;
        const __half* hv = (const __half*)&areg[j];
#pragma unroll
        for (int m = 0; m < 8; m++) {
            int p = q8 * 8 + m, k = p / 3, c = p - 3 * k;
            As[0][(c * 64 + r) * AKH + k] = hv[m];
        }
    }
#pragma unroll
    for (int j = 0; j < 6; j++) {
        int l = tid + j * 384;
        if (l < 2048) { int o = l >> 5, k = l & 31; Ws[0][o * AKH + k] = __float2half(wreg[j]); }
    }
    __syncthreads();

    for (int kc = 0; kc < NC; kc++) {
        int cur = kc & 1, nb = cur ^ 1;
        bool more = (kc + 1 < NC);
        if (more) {
            int k0 = (kc + 1) * 32;
#pragma unroll
            for (int j = 0; j < 2; j++) {
                int l = tid + j * 384, r = l / 12, q8 = l % 12;
                areg[j] = *(const uint4*)(g_ao + (size_t)(bn0 + r) * (DINNER * COOR) + k0 * 3 + q8 * 8);
            }
#pragma unroll
            for (int j = 0; j < 6; j++) {
                int l = tid + j * 384;
                if (l < 2048) { int o = l >> 5, k = l & 31; wreg[j] = Wo[(size_t)(o0 + o) * DINNER + k0 + k]; }
            }
        }

        const __half* A  = As[cur];
        const __half* Wt = Ws[cur];
#pragma unroll
        for (int ks = 0; ks < 2; ks++) {
            unsigned a[4];
            a[0] = *(const unsigned*)(A + (m0 + gID)     * AKH + 16 * ks + 2 * tig);
            a[1] = *(const unsigned*)(A + (m0 + gID + 8) * AKH + 16 * ks + 2 * tig);
            a[2] = *(const unsigned*)(A + (m0 + gID)     * AKH + 16 * ks + 2 * tig + 8);
            a[3] = *(const unsigned*)(A + (m0 + gID + 8) * AKH + 16 * ks + 2 * tig + 8);
#pragma unroll
            for (int nt = 0; nt < 8; nt++) {
                unsigned bf[2];
                bf[0] = *(const unsigned*)(Wt + (8 * nt + gID) * AKH + 16 * ks + 2 * tig);
                bf[1] = *(const unsigned*)(Wt + (8 * nt + gID) * AKH + 16 * ks + 2 * tig + 8);
                mma_f16(o_acc[nt], a, bf);
            }
        }

        if (more) {
#pragma unroll
            for (int j = 0; j < 2; j++) {
                int l = tid + j * 384, r = l / 12, q8 = l % 12;
                const __half* hv = (const __half*)&areg[j];
#pragma unroll
                for (int m = 0; m < 8; m++) {
                    int p = q8 * 8 + m, k = p / 3, c = p - 3 * k;
                    As[nb][(c * 64 + r) * AKH + k] = hv[m];
                }
            }
#pragma unroll
            for (int j = 0; j < 6; j++) {
                int l = tid + j * 384;
                if (l < 2048) { int o = l >> 5, k = l & 31; Ws[nb][o * AKH + k] = __float2half(wreg[j]); }
            }
        }
        __syncthreads();
    }

    // epilogue: out[bn][o][c] fp32
#pragma unroll
    for (int i = 0; i < 2; i++) {
        int arow = m0 + gID + 8 * i;
        int c = arow >> 6, bnl = arow & 63;
        int bn = bn0 + bnl;
#pragma unroll
        for (int nt = 0; nt < 8; nt++) {
#pragma unroll
            for (int hh = 0; hh < 2; hh++) {
                int o = o0 + 8 * nt + 2 * tig + hh;
                out[((size_t)bn * CIN + o) * 3 + c] = o_acc[nt][2 * i + hh];
            }
        }
    }
}

// ---------------------------------------------------------------------------
extern "C" void kernel_launch(void* const* d_in, const int* in_sizes, int n_in,
                              void* d_out, int out_size)
{
    const float* x  = (const float*)d_in[0];
    const float* Wq = (const float*)d_in[1];
    const float* Wk = (const float*)d_in[2];
    const float* Wv = (const float*)d_in[3];
    const float* Wo = (const float*)d_in[4];
    float* out = (float*)d_out;

    const int pj_smem   = (2 * 192 * AKH + 2 * 64 * AKH) * 2;   // 40960 B
    const int attn_smem = SMTOT_H * 2;                          // 114688 B

    cudaFuncSetAttribute(qkv3_kernel,
                         cudaFuncAttributeMaxDynamicSharedMemorySize, pj_smem);
    cudaFuncSetAttribute(attn3_kernel,
                         cudaFuncAttributeMaxDynamicSharedMemorySize, attn_smem);
    cudaFuncSetAttribute(oproj3_kernel,
                         cudaFuncAttributeMaxDynamicSharedMemorySize, pj_smem);

    qkv3_kernel<<<dim3(BDIM * NSEQ / 64, DINNER / 64, 3), 384, pj_smem>>>(x, Wq, Wk, Wv);
    attn3_kernel<<<dim3(NSEQ / 128, BDIM * HEADS), 256, attn_smem>>>();
    oproj3_kernel<<<dim3(BDIM * NSEQ / 64, CIN / 64), 384, pj_smem>>>(Wo, out);
}

// round 9
// speedup vs baseline: 5.2288x; 1.4449x over previous
#include <cuda_runtime.h>
#include <cuda_fp16.h>
#include <math.h>
#include <stdint.h>

#define BDIM   2
#define NSEQ   2048
#define CIN    256
#define COOR   3
#define HEADS  8
#define DHEAD  64
#define DINNER 512
#define EDIM   192

// attention tiling (halves)
#define QSTRH  200   // Q/K smem row stride: 400B -> conflict-free ldmatrix rows
#define VSTRH  200   // V row-major stride (same property)
#define PSTRH  40    // P row stride: 80B -> conflict-free
#define KVT    32
#define NKT    (NSEQ/KVT)

// projection tiling
#define AKH    40    // A/W smem stride (halves)

// Scratch (fp16)
__device__ __half g_q [BDIM*HEADS*NSEQ*EDIM];
__device__ __half g_k [BDIM*HEADS*NSEQ*EDIM];
__device__ __half g_v [BDIM*HEADS*NSEQ*EDIM];
__device__ __half g_ao[BDIM*NSEQ*DINNER*COOR];

__device__ __forceinline__ void mma_f16(float* c, const unsigned* a, const unsigned* b) {
    asm volatile(
        "mma.sync.aligned.m16n8k16.row.col.f32.f16.f16.f32 "
        "{%0,%1,%2,%3}, {%4,%5,%6,%7}, {%8,%9}, {%0,%1,%2,%3};"
        : "+f"(c[0]), "+f"(c[1]), "+f"(c[2]), "+f"(c[3])
        : "r"(a[0]), "r"(a[1]), "r"(a[2]), "r"(a[3]), "r"(b[0]), "r"(b[1]));
}

__device__ __forceinline__ void ldsm_x4(unsigned* r, uint32_t addr) {
    asm volatile("ldmatrix.sync.aligned.m8n8.x4.shared.b16 {%0,%1,%2,%3}, [%4];"
        : "=r"(r[0]), "=r"(r[1]), "=r"(r[2]), "=r"(r[3]) : "r"(addr));
}
__device__ __forceinline__ void ldsm_x4_t(unsigned* r, uint32_t addr) {
    asm volatile("ldmatrix.sync.aligned.m8n8.x4.trans.shared.b16 {%0,%1,%2,%3}, [%4];"
        : "=r"(r[0]), "=r"(r[1]), "=r"(r[2]), "=r"(r[3]) : "r"(addr));
}

__device__ __forceinline__ uint32_t smem_u32(const void* p) {
    uint32_t a;
    asm("{ .reg .u64 t; cvta.to.shared.u64 t, %1; cvt.u32.u64 %0, t; }"
        : "=r"(a) : "l"(p));
    return a;
}
__device__ __forceinline__ void cp16(uint32_t dst, const void* src) {
    asm volatile("cp.async.ca.shared.global [%0], [%1], 16;" :: "r"(dst), "l"(src));
}
#define CP_COMMIT() asm volatile("cp.async.commit_group;" ::: "memory")
#define CP_WAIT0()  asm volatile("cp.async.wait_group 0;" ::: "memory")

// ===========================================================================
// Kernel 1: QKV projection, fp16 mma (unchanged from R8).
// ===========================================================================
__global__ __launch_bounds__(384, 1) void qkv3_kernel(
    const float* __restrict__ x,
    const float* __restrict__ Wq,
    const float* __restrict__ Wk,
    const float* __restrict__ Wv)
{
    extern __shared__ __half smh[];
    __half* As[2] = { smh, smh + 192 * AKH };
    __half* Ws[2] = { smh + 2 * 192 * AKH, smh + 2 * 192 * AKH + 64 * AKH };

    int wsel = blockIdx.z;
    const float* W    = (wsel == 0) ? Wq : (wsel == 1 ? Wk : Wv);
    __half*      outp = (wsel == 0) ? g_q : (wsel == 1 ? g_k : g_v);

    int bn0 = blockIdx.x * 64;
    int o0  = blockIdx.y * 64;
    int tid = threadIdx.x;
    int warp = tid >> 5, lane = tid & 31;
    int gID = lane >> 2, tig = lane & 3;
    int m0  = warp * 16;

    float o_acc[8][4];
#pragma unroll
    for (int nt = 0; nt < 8; nt++)
#pragma unroll
        for (int i = 0; i < 4; i++) o_acc[nt][i] = 0.f;

    const int NC = CIN / 32;
    float4 areg[4];
    float  wreg[6];

#pragma unroll
    for (int j = 0; j < 4; j++) {
        int l = tid + j * 384, r = l / 24, q4 = l % 24;
        areg[j] = *(const float4*)(x + (size_t)(bn0 + r) * (CIN * COOR) + q4 * 4);
    }
#pragma unroll
    for (int j = 0; j < 6; j++) {
        int l = tid + j * 384;
        if (l < 2048) { int o = l >> 5, k = l & 31; wreg[j] = W[(size_t)(o0 + o) * CIN + k]; }
    }
#pragma unroll
    for (int j = 0; j < 4; j++) {
        int l = tid + j * 384, r = l / 24, q4 = l % 24;
        float f[4] = { areg[j].x, areg[j].y, areg[j].z, areg[j].w };
#pragma unroll
        for (int m = 0; m < 4; m++) {
            int p = q4 * 4 + m, k = p / 3, c = p - 3 * k;
            As[0][(c * 64 + r) * AKH + k] = __float2half(f[m]);
        }
    }
#pragma unroll
    for (int j = 0; j < 6; j++) {
        int l = tid + j * 384;
        if (l < 2048) { int o = l >> 5, k = l & 31; Ws[0][o * AKH + k] = __float2half(wreg[j]); }
    }
    __syncthreads();

    for (int kc = 0; kc < NC; kc++) {
        int cur = kc & 1, nb = cur ^ 1;
        bool more = (kc + 1 < NC);
        if (more) {
            int k0 = (kc + 1) * 32;
#pragma unroll
            for (int j = 0; j < 4; j++) {
                int l = tid + j * 384, r = l / 24, q4 = l % 24;
                areg[j] = *(const float4*)(x + (size_t)(bn0 + r) * (CIN * COOR) + k0 * 3 + q4 * 4);
            }
#pragma unroll
            for (int j = 0; j < 6; j++) {
                int l = tid + j * 384;
                if (l < 2048) { int o = l >> 5, k = l & 31; wreg[j] = W[(size_t)(o0 + o) * CIN + k0 + k]; }
            }
        }

        const __half* A  = As[cur];
        const __half* Wt = Ws[cur];
#pragma unroll
        for (int ks = 0; ks < 2; ks++) {
            unsigned a[4];
            a[0] = *(const unsigned*)(A + (m0 + gID)     * AKH + 16 * ks + 2 * tig);
            a[1] = *(const unsigned*)(A + (m0 + gID + 8) * AKH + 16 * ks + 2 * tig);
            a[2] = *(const unsigned*)(A + (m0 + gID)     * AKH + 16 * ks + 2 * tig + 8);
            a[3] = *(const unsigned*)(A + (m0 + gID + 8) * AKH + 16 * ks + 2 * tig + 8);
#pragma unroll
            for (int nt = 0; nt < 8; nt++) {
                unsigned bf[2];
                bf[0] = *(const unsigned*)(Wt + (8 * nt + gID) * AKH + 16 * ks + 2 * tig);
                bf[1] = *(const unsigned*)(Wt + (8 * nt + gID) * AKH + 16 * ks + 2 * tig + 8);
                mma_f16(o_acc[nt], a, bf);
            }
        }

        if (more) {
#pragma unroll
            for (int j = 0; j < 4; j++) {
                int l = tid + j * 384, r = l / 24, q4 = l % 24;
                float f[4] = { areg[j].x, areg[j].y, areg[j].z, areg[j].w };
#pragma unroll
                for (int m = 0; m < 4; m++) {
                    int p = q4 * 4 + m, k = p / 3, c = p - 3 * k;
                    As[nb][(c * 64 + r) * AKH + k] = __float2half(f[m]);
                }
            }
#pragma unroll
            for (int j = 0; j < 6; j++) {
                int l = tid + j * 384;
                if (l < 2048) { int o = l >> 5, k = l & 31; Ws[nb][o * AKH + k] = __float2half(wreg[j]); }
            }
        }
        __syncthreads();
    }

#pragma unroll
    for (int i = 0; i < 2; i++) {
        int arow = m0 + gID + 8 * i;
        int c = arow >> 6, bnl = arow & 63;
        int bn = bn0 + bnl;
        int b = bn >> 11, n = bn & (NSEQ - 1);
#pragma unroll
        for (int nt = 0; nt < 8; nt++) {
#pragma unroll
            for (int hh = 0; hh < 2; hh++) {
                int o = o0 + 8 * nt + 2 * tig + hh;
                int hd = o >> 6, d = o & 63;
                outp[((size_t)(b * HEADS + hd) * NSEQ + n) * EDIM + d * 3 + c] =
                    __float2half(o_acc[nt][2 * i + hh]);
            }
        }
    }
}

// ===========================================================================
// Kernel 2: flash attention, fp16 mma + ldmatrix, cp.async K AND V (no
// transpose; PV B-frags via ldmatrix.trans).  grid (NSEQ/128, B*H), block 256.
// ===========================================================================
#define SMQ  0
#define SMK  (128*QSTRH)                   // 25600
#define SMV  (SMK + 2*KVT*QSTRH)           // 38400
#define SMP  (SMV + 2*KVT*VSTRH)           // 51200
#define SMTOT_H (SMP + 8*16*PSTRH)         // 56320 halves = 112640 B

__global__ __launch_bounds__(256, 1) void attn4_kernel()
{
    extern __shared__ __half smh[];
    __half* Qs = smh + SMQ;
    __half* Ps = smh + SMP;

    uint32_t q_u  = smem_u32(smh + SMQ);
    uint32_t k_u[2] = { smem_u32(smh + SMK), smem_u32(smh + SMK + KVT * QSTRH) };
    uint32_t v_u[2] = { smem_u32(smh + SMV), smem_u32(smh + SMV + KVT * VSTRH) };

    int tid  = threadIdx.x;
    int warp = tid >> 5, lane = tid & 31;
    int gID  = lane >> 2, tig = lane & 3;
    int bh   = blockIdx.y;
    int b    = bh >> 3, h = bh & 7;
    int row0 = blockIdx.x * 128;
    int m0   = warp * 16;

    const __half* qb = g_q + (size_t)bh * NSEQ * EDIM;
    const __half* kb = g_k + (size_t)bh * NSEQ * EDIM;
    const __half* vb = g_v + (size_t)bh * NSEQ * EDIM;

    // ldmatrix address components
    int l7   = lane & 7;
    int lh8  = (lane >> 3) & 1;   // +8 within pair
    int lh16 = lane >> 4;         // high half
    // Q a-frag: row = m0 + l7 + 8*lh8, col8 = 8*lh16
    uint32_t qa_off = (uint32_t)((m0 + l7 + 8 * lh8) * QSTRH + 8 * lh16) * 2;
    // K b-frag: row(p) = 16p + l7 + 8*lh16, col8 = 8*lh8
    uint32_t kb_off = (uint32_t)((l7 + 8 * lh16) * QSTRH + 8 * lh8) * 2;
    // P a-frag: row = l7 + 8*lh8, col8 = 8*lh16
    uint32_t pw_u   = smem_u32(Ps + warp * 16 * PSTRH);
    uint32_t pa_off = (uint32_t)((l7 + 8 * lh8) * PSTRH + 8 * lh16) * 2;
    // V b-frag (trans): row(kt) = 16kt + l7 + 8*lh8, col8 = 8*lh16
    uint32_t vb_off = (uint32_t)((l7 + 8 * lh8) * VSTRH + 8 * lh16) * 2;

    // load Q tile: 128 rows x 24 uint4 = 3072 -> 12 per thread
#pragma unroll
    for (int j = 0; j < 12; j++) {
        int l = tid + j * 256, r = l / 24, e8 = l % 24;
        *(uint4*)(Qs + r * QSTRH + e8 * 8) =
            *(const uint4*)(qb + (size_t)(row0 + r) * EDIM + e8 * 8);
    }

    float o_acc[24][4];
#pragma unroll
    for (int nt = 0; nt < 24; nt++)
#pragma unroll
        for (int i = 0; i < 4; i++) o_acc[nt][i] = 0.f;
    float lsum0 = 0.f, lsum1 = 0.f;

    const float scl2 = 0.07216878364870322f * 1.4426950408889634f;  // /sqrt(192)*log2e
    __half* Pw = Ps + warp * 16 * PSTRH;

    // prologue: tile 0 (K+V via cp.async, 3 x 16B each per thread)
    {
#pragma unroll
        for (int j = 0; j < 3; j++) {
            int l = tid + j * 256, r = l / 24, e8 = l % 24;
            cp16(k_u[0] + (uint32_t)(r * QSTRH + e8 * 8) * 2, kb + (size_t)r * EDIM + e8 * 8);
            cp16(v_u[0] + (uint32_t)(r * VSTRH + e8 * 8) * 2, vb + (size_t)r * EDIM + e8 * 8);
        }
        CP_COMMIT();
        CP_WAIT0();
    }
    __syncthreads();

    for (int t = 0; t < NKT; t++) {
        int cur = t & 1, nb = cur ^ 1;
        bool more = (t + 1 < NKT);

        if (more) {
            const __half* kbt = kb + (size_t)(t + 1) * KVT * EDIM;
            const __half* vbt = vb + (size_t)(t + 1) * KVT * EDIM;
#pragma unroll
            for (int j = 0; j < 3; j++) {
                int l = tid + j * 256, r = l / 24, e8 = l % 24;
                cp16(k_u[nb] + (uint32_t)(r * QSTRH + e8 * 8) * 2, kbt + (size_t)r * EDIM + e8 * 8);
                cp16(v_u[nb] + (uint32_t)(r * VSTRH + e8 * 8) * 2, vbt + (size_t)r * EDIM + e8 * 8);
            }
            CP_COMMIT();
        }

        // ---- S = Q K^T : 16 x 32 per warp, 12 k16-steps, ldmatrix frags ----
        float s[4][4];
#pragma unroll
        for (int nt = 0; nt < 4; nt++)
#pragma unroll
            for (int i = 0; i < 4; i++) s[nt][i] = 0.f;

#pragma unroll
        for (int ks = 0; ks < 12; ks++) {
            unsigned a[4];
            ldsm_x4(a, q_u + qa_off + (uint32_t)(16 * ks) * 2);
#pragma unroll
            for (int p = 0; p < 2; p++) {
                unsigned bb[4];
                ldsm_x4(bb, k_u[cur] + kb_off + (uint32_t)(16 * p * QSTRH + 16 * ks) * 2);
                mma_f16(s[2 * p],     a, bb);
                mma_f16(s[2 * p + 1], a, bb + 2);
            }
        }

        // ---- unnormalized exp2 + P staging (fp16) ----
#pragma unroll
        for (int nt = 0; nt < 4; nt++) {
            float p0 = exp2f(s[nt][0] * scl2);
            float p1 = exp2f(s[nt][1] * scl2);
            float p2 = exp2f(s[nt][2] * scl2);
            float p3 = exp2f(s[nt][3] * scl2);
            lsum0 += p0 + p1;
            lsum1 += p2 + p3;
            *(__half2*)(Pw + gID       * PSTRH + 8 * nt + 2 * tig) = __floats2half2_rn(p0, p1);
            *(__half2*)(Pw + (gID + 8) * PSTRH + 8 * nt + 2 * tig) = __floats2half2_rn(p2, p3);
        }
        __syncwarp();

        // ---- O += P V : 2 k16-steps, 24 n-tiles, V frags via ldmatrix.trans ----
#pragma unroll
        for (int kt = 0; kt < 2; kt++) {
            unsigned a[4];
            ldsm_x4(a, pw_u + pa_off + (uint32_t)(16 * kt) * 2);
#pragma unroll
            for (int g = 0; g < 12; g++) {
                unsigned vv[4];
                ldsm_x4_t(vv, v_u[cur] + vb_off + (uint32_t)(16 * kt * VSTRH + 16 * g) * 2);
                mma_f16(o_acc[2 * g],     a, vv);
                mma_f16(o_acc[2 * g + 1], a, vv + 2);
            }
        }

        if (more) CP_WAIT0();
        __syncthreads();
    }

    // reduce row sums across the 4 tig lanes
    lsum0 += __shfl_xor_sync(0xffffffffu, lsum0, 1);
    lsum0 += __shfl_xor_sync(0xffffffffu, lsum0, 2);
    lsum1 += __shfl_xor_sync(0xffffffffu, lsum1, 1);
    lsum1 += __shfl_xor_sync(0xffffffffu, lsum1, 2);
    float inv0 = 1.f / lsum0, inv1 = 1.f / lsum1;

    int n0 = row0 + m0 + gID;
    int n1 = n0 + 8;
    __half* d0 = g_ao + ((size_t)b * NSEQ + n0) * (DINNER * COOR) + h * EDIM;
    __half* d1 = g_ao + ((size_t)b * NSEQ + n1) * (DINNER * COOR) + h * EDIM;
#pragma unroll
    for (int nt = 0; nt < 24; nt++) {
#pragma unroll
        for (int hh = 0; hh < 2; hh++) {
            int e = 8 * nt + 2 * tig + hh;
            d0[e] = __float2half(o_acc[nt][hh]     * inv0);
            d1[e] = __float2half(o_acc[nt][2 + hh] * inv1);
        }
    }
}

// ===========================================================================
// Kernel 3: output projection, fp16 mma (unchanged from R8).
// ===========================================================================
__global__ __launch_bounds__(384, 1) void oproj3_kernel(
    const float* __restrict__ Wo, float* __restrict__ out)
{
    extern __shared__ __half smh[];
    __half* As[2] = { smh, smh + 192 * AKH };
    __half* Ws[2] = { smh + 2 * 192 * AKH, smh + 2 * 192 * AKH + 64 * AKH };

    int bn0 = blockIdx.x * 64;
    int o0  = blockIdx.y * 64;
    int tid = threadIdx.x;
    int warp = tid >> 5, lane = tid & 31;
    int gID = lane >> 2, tig = lane & 3;
    int m0  = warp * 16;

    float o_acc[8][4];
#pragma unroll
    for (int nt = 0; nt < 8; nt++)
#pragma unroll
        for (int i = 0; i < 4; i++) o_acc[nt][i] = 0.f;

    const int NC = DINNER / 32;
    uint4 areg[2];
    float wreg[6];

#pragma unroll
    for (int j = 0; j < 2; j++) {
        int l = tid + j * 384, r = l / 12, q8 = l % 12;
        areg[j] = *(const uint4*)(g_ao + (size_t)(bn0 + r) * (DINNER * COOR) + q8 * 8);
    }
#pragma unroll
    for (int j = 0; j < 6; j++) {
        int l = tid + j * 384;
        if (l < 2048) { int o = l >> 5, k = l & 31; wreg[j] = Wo[(size_t)(o0 + o) * DINNER + k]; }
    }
#pragma unroll
    for (int j = 0; j < 2; j++) {
        int l = tid + j * 384, r = l / 12, q8 = l % 12;
        const __half* hv = (const __half*)&areg[j];
#pragma unroll
        for (int m = 0; m < 8; m++) {
            int p = q8 * 8 + m, k = p / 3, c = p - 3 * k;
            As[0][(c * 64 + r) * AKH + k] = hv[m];
        }
    }
#pragma unroll
    for (int j = 0; j < 6; j++) {
        int l = tid + j * 384;
        if (l < 2048) { int o = l >> 5, k = l & 31; Ws[0][o * AKH + k] = __float2half(wreg[j]); }
    }
    __syncthreads();

    for (int kc = 0; kc < NC; kc++) {
        int cur = kc & 1, nb = cur ^ 1;
        bool more = (kc + 1 < NC);
        if (more) {
            int k0 = (kc + 1) * 32;
#pragma unroll
            for (int j = 0; j < 2; j++) {
                int l = tid + j * 384, r = l / 12, q8 = l % 12;
                areg[j] = *(const uint4*)(g_ao + (size_t)(bn0 + r) * (DINNER * COOR) + k0 * 3 + q8 * 8);
            }
#pragma unroll
            for (int j = 0; j < 6; j++) {
                int l = tid + j * 384;
                if (l < 2048) { int o = l >> 5, k = l & 31; wreg[j] = Wo[(size_t)(o0 + o) * DINNER + k0 + k]; }
            }
        }

        const __half* A  = As[cur];
        const __half* Wt = Ws[cur];
#pragma unroll
        for (int ks = 0; ks < 2; ks++) {
            unsigned a[4];
            a[0] = *(const unsigned*)(A + (m0 + gID)     * AKH + 16 * ks + 2 * tig);
            a[1] = *(const unsigned*)(A + (m0 + gID + 8) * AKH + 16 * ks + 2 * tig);
            a[2] = *(const unsigned*)(A + (m0 + gID)     * AKH + 16 * ks + 2 * tig + 8);
            a[3] = *(const unsigned*)(A + (m0 + gID + 8) * AKH + 16 * ks + 2 * tig + 8);
#pragma unroll
            for (int nt = 0; nt < 8; nt++) {
                unsigned bf[2];
                bf[0] = *(const unsigned*)(Wt + (8 * nt + gID) * AKH + 16 * ks + 2 * tig);
                bf[1] = *(const unsigned*)(Wt + (8 * nt + gID) * AKH + 16 * ks + 2 * tig + 8);
                mma_f16(o_acc[nt], a, bf);
            }
        }

        if (more) {
#pragma unroll
            for (int j = 0; j < 2; j++) {
                int l = tid + j * 384, r = l / 12, q8 = l % 12;
                const __half* hv = (const __half*)&areg[j];
#pragma unroll
                for (int m = 0; m < 8; m++) {
                    int p = q8 * 8 + m, k = p / 3, c = p - 3 * k;
                    As[nb][(c * 64 + r) * AKH + k] = hv[m];
                }
            }
#pragma unroll
            for (int j = 0; j < 6; j++) {
                int l = tid + j * 384;
                if (l < 2048) { int o = l >> 5, k = l & 31; Ws[nb][o * AKH + k] = __float2half(wreg[j]); }
            }
        }
        __syncthreads();
    }

#pragma unroll
    for (int i = 0; i < 2; i++) {
        int arow = m0 + gID + 8 * i;
        int c = arow >> 6, bnl = arow & 63;
        int bn = bn0 + bnl;
#pragma unroll
        for (int nt = 0; nt < 8; nt++) {
#pragma unroll
            for (int hh = 0; hh < 2; hh++) {
                int o = o0 + 8 * nt + 2 * tig + hh;
                out[((size_t)bn * CIN + o) * 3 + c] = o_acc[nt][2 * i + hh];
            }
        }
    }
}

// ---------------------------------------------------------------------------
extern "C" void kernel_launch(void* const* d_in, const int* in_sizes, int n_in,
                              void* d_out, int out_size)
{
    const float* x  = (const float*)d_in[0];
    const float* Wq = (const float*)d_in[1];
    const float* Wk = (const float*)d_in[2];
    const float* Wv = (const float*)d_in[3];
    const float* Wo = (const float*)d_in[4];
    float* out = (float*)d_out;

    const int pj_smem   = (2 * 192 * AKH + 2 * 64 * AKH) * 2;   // 40960 B
    const int attn_smem = SMTOT_H * 2;                          // 112640 B

    cudaFuncSetAttribute(qkv3_kernel,
                         cudaFuncAttributeMaxDynamicSharedMemorySize, pj_smem);
    cudaFuncSetAttribute(attn4_kernel,
                         cudaFuncAttributeMaxDynamicSharedMemorySize, attn_smem);
    cudaFuncSetAttribute(oproj3_kernel,
                         cudaFuncAttributeMaxDynamicSharedMemorySize, pj_smem);

    qkv3_kernel<<<dim3(BDIM * NSEQ / 64, DINNER / 64, 3), 384, pj_smem>>>(x, Wq, Wk, Wv);
    attn4_kernel<<<dim3(NSEQ / 128, BDIM * HEADS), 256, attn_smem>>>();
    oproj3_kernel<<<dim3(BDIM * NSEQ / 64, CIN / 64), 384, pj_smem>>>(Wo, out);
}

// round 10
// speedup vs baseline: 6.2454x; 1.1944x over previous
#include <cuda_runtime.h>
#include <cuda_fp16.h>
#include <math.h>
#include <stdint.h>

#define BDIM   2
#define NSEQ   2048
#define CIN    256
#define COOR   3
#define HEADS  8
#define DHEAD  64
#define DINNER 512
#define EDIM   192
#define BN     (BDIM*NSEQ)     // 4096

// attention tiling (halves)
#define QSTRH  200
#define VSTRH  200
#define PSTRH  40
#define KVT    32
#define NKT    (NSEQ/KVT)

// projection tiling
#define AKH    40    // oproj3 strides
#define AK2    72    // qkv4 smem row stride (halves): 144B -> conflict-free ldsm
#define KC     64    // qkv4 K-chunk
#define NCQ    (CIN/KC)   // 4

// Scratch (fp16)
__device__ __half g_q [BDIM*HEADS*NSEQ*EDIM];
__device__ __half g_k [BDIM*HEADS*NSEQ*EDIM];
__device__ __half g_v [BDIM*HEADS*NSEQ*EDIM];
__device__ __half g_ao[BDIM*NSEQ*DINNER*COOR];
__device__ __half g_xh[COOR*BN*CIN];        // [c][bn][i] k-major planes
__device__ __half g_wh[3*DINNER*CIN];       // [wsel][o][i]

__device__ __forceinline__ void mma_f16(float* c, const unsigned* a, const unsigned* b) {
    asm volatile(
        "mma.sync.aligned.m16n8k16.row.col.f32.f16.f16.f32 "
        "{%0,%1,%2,%3}, {%4,%5,%6,%7}, {%8,%9}, {%0,%1,%2,%3};"
        : "+f"(c[0]), "+f"(c[1]), "+f"(c[2]), "+f"(c[3])
        : "r"(a[0]), "r"(a[1]), "r"(a[2]), "r"(a[3]), "r"(b[0]), "r"(b[1]));
}
__device__ __forceinline__ void ldsm_x4(unsigned* r, uint32_t addr) {
    asm volatile("ldmatrix.sync.aligned.m8n8.x4.shared.b16 {%0,%1,%2,%3}, [%4];"
        : "=r"(r[0]), "=r"(r[1]), "=r"(r[2]), "=r"(r[3]) : "r"(addr));
}
__device__ __forceinline__ void ldsm_x4_t(unsigned* r, uint32_t addr) {
    asm volatile("ldmatrix.sync.aligned.m8n8.x4.trans.shared.b16 {%0,%1,%2,%3}, [%4];"
        : "=r"(r[0]), "=r"(r[1]), "=r"(r[2]), "=r"(r[3]) : "r"(addr));
}
__device__ __forceinline__ uint32_t smem_u32(const void* p) {
    uint32_t a;
    asm("{ .reg .u64 t; cvta.to.shared.u64 t, %1; cvt.u32.u64 %0, t; }"
        : "=r"(a) : "l"(p));
    return a;
}
__device__ __forceinline__ void cp16(uint32_t dst, const void* src) {
    asm volatile("cp.async.ca.shared.global [%0], [%1], 16;" :: "r"(dst), "l"(src));
}
#define CP_COMMIT() asm volatile("cp.async.commit_group;" ::: "memory")
#define CP_WAITN(n) asm volatile("cp.async.wait_group %0;" :: "n"(n) : "memory")

// ===========================================================================
// Converts
// ===========================================================================
__global__ __launch_bounds__(256) void conv_x_kernel(const float* __restrict__ x)
{
    int idx = blockIdx.x * 256 + threadIdx.x;   // (bn, i) pair; grid = BN*CIN/256
#pragma unroll
    for (int c = 0; c < 3; c++)
        g_xh[c * (BN * CIN) + idx] = __float2half(x[(size_t)idx * 3 + c]);
}
__global__ __launch_bounds__(256) void conv_w_kernel(
    const float* __restrict__ Wq, const float* __restrict__ Wk,
    const float* __restrict__ Wv)
{
    int idx = blockIdx.x * 256 + threadIdx.x;   // grid = 3*DINNER*CIN/256
    int wsel = idx / (DINNER * CIN), rem = idx % (DINNER * CIN);
    const float* W = (wsel == 0) ? Wq : (wsel == 1 ? Wk : Wv);
    g_wh[idx] = __float2half(W[rem]);
}

// ===========================================================================
// Kernel 1: QKV GEMM, fp16, cp.async 3-stage + ldmatrix.
// grid (BN/128, DINNER/64, 9 = wsel*3+c), block 256 (8 warps).
// ===========================================================================
#define QKV_AOFF(s)  ((s) * 128 * AK2)
#define QKV_WBASE    (3 * 128 * AK2)                 // 27648 halves
#define QKV_WOFF(s)  (QKV_WBASE + (s) * 64 * AK2)
#define QKV_SMEMH    (QKV_WBASE + 3 * 64 * AK2)      // 41472 halves = 82944 B

__global__ __launch_bounds__(256, 2) void qkv4_kernel()
{
    extern __shared__ __half smh[];
    uint32_t sb = smem_u32(smh);

    int z    = blockIdx.z;
    int wsel = z / 3, cc = z % 3;
    __half* outp = (wsel == 0) ? g_q : (wsel == 1 ? g_k : g_v);
    const __half* Ap = g_xh + (size_t)cc * (BN * CIN);
    const __half* Wp = g_wh + (size_t)wsel * (DINNER * CIN);

    int bn0 = blockIdx.x * 128;
    int o0  = blockIdx.y * 64;
    int tid = threadIdx.x;
    int warp = tid >> 5, lane = tid & 31;
    int gID = lane >> 2, tig = lane & 3;
    int m0  = warp * 16;

    int l7   = lane & 7;
    int lh8  = (lane >> 3) & 1;
    int lh16 = lane >> 4;
    uint32_t a_off = (uint32_t)((m0 + l7 + 8 * lh8) * AK2 + 8 * lh16) * 2;
    uint32_t b_off = (uint32_t)((l7 + 8 * lh16) * AK2 + 8 * lh8) * 2;

    float o_acc[8][4];
#pragma unroll
    for (int nt = 0; nt < 8; nt++)
#pragma unroll
        for (int i = 0; i < 4; i++) o_acc[nt][i] = 0.f;

    // issue helper (A: 4x16B, W: 2x16B per thread)
    auto issue = [&](int stage, int kc) {
        int k0 = kc * KC;
#pragma unroll
        for (int j = 0; j < 4; j++) {
            int l = tid + j * 256, r = l >> 3, seg = l & 7;
            cp16(sb + (QKV_AOFF(stage) + r * AK2 + seg * 8) * 2,
                 Ap + (size_t)(bn0 + r) * CIN + k0 + seg * 8);
        }
#pragma unroll
        for (int j = 0; j < 2; j++) {
            int l = tid + j * 256, r = l >> 3, seg = l & 7;
            cp16(sb + (QKV_WOFF(stage) + r * AK2 + seg * 8) * 2,
                 Wp + (size_t)(o0 + r) * CIN + k0 + seg * 8);
        }
        CP_COMMIT();
    };

    issue(0, 0);
    issue(1, 1);

    for (int kc = 0; kc < NCQ; kc++) {
        if (kc + 2 < NCQ) issue((kc + 2) % 3, kc + 2);
        if (kc <= 1)      CP_WAITN(2);
        else if (kc == 2) CP_WAITN(1);
        else              CP_WAITN(0);
        __syncthreads();

        uint32_t ab = sb + QKV_AOFF(kc % 3) * 2 + a_off;
        uint32_t wb = sb + QKV_WOFF(kc % 3) * 2 + b_off;
#pragma unroll
        for (int ks = 0; ks < KC / 16; ks++) {
            unsigned a[4];
            ldsm_x4(a, ab + (uint32_t)(16 * ks) * 2);
#pragma unroll
            for (int p = 0; p < 4; p++) {
                unsigned bb[4];
                ldsm_x4(bb, wb + (uint32_t)(16 * p * AK2 + 16 * ks) * 2);
                mma_f16(o_acc[2 * p],     a, bb);
                mma_f16(o_acc[2 * p + 1], a, bb + 2);
            }
        }
        __syncthreads();
    }

    // epilogue -> split-head fp16
#pragma unroll
    for (int i = 0; i < 2; i++) {
        int bn = bn0 + m0 + gID + 8 * i;
        int b = bn >> 11, n = bn & (NSEQ - 1);
#pragma unroll
        for (int nt = 0; nt < 8; nt++) {
#pragma unroll
            for (int hh = 0; hh < 2; hh++) {
                int o = o0 + 8 * nt + 2 * tig + hh;
                int hd = o >> 6, d = o & 63;
                outp[((size_t)(b * HEADS + hd) * NSEQ + n) * EDIM + d * 3 + cc] =
                    __float2half(o_acc[nt][2 * i + hh]);
            }
        }
    }
}

// ===========================================================================
// Kernel 2: flash attention (unchanged from R9)
// ===========================================================================
#define SMQ  0
#define SMK  (128*QSTRH)
#define SMV  (SMK + 2*KVT*QSTRH)
#define SMP  (SMV + 2*KVT*VSTRH)
#define SMTOT_H (SMP + 8*16*PSTRH)

__global__ __launch_bounds__(256, 1) void attn4_kernel()
{
    extern __shared__ __half smh[];
    __half* Qs = smh + SMQ;
    __half* Ps = smh + SMP;

    uint32_t q_u  = smem_u32(smh + SMQ);
    uint32_t k_u[2] = { smem_u32(smh + SMK), smem_u32(smh + SMK + KVT * QSTRH) };
    uint32_t v_u[2] = { smem_u32(smh + SMV), smem_u32(smh + SMV + KVT * VSTRH) };

    int tid  = threadIdx.x;
    int warp = tid >> 5, lane = tid & 31;
    int gID  = lane >> 2, tig = lane & 3;
    int bh   = blockIdx.y;
    int b    = bh >> 3, h = bh & 7;
    int row0 = blockIdx.x * 128;
    int m0   = warp * 16;

    const __half* qb = g_q + (size_t)bh * NSEQ * EDIM;
    const __half* kb = g_k + (size_t)bh * NSEQ * EDIM;
    const __half* vb = g_v + (size_t)bh * NSEQ * EDIM;

    int l7   = lane & 7;
    int lh8  = (lane >> 3) & 1;
    int lh16 = lane >> 4;
    uint32_t qa_off = (uint32_t)((m0 + l7 + 8 * lh8) * QSTRH + 8 * lh16) * 2;
    uint32_t kb_off = (uint32_t)((l7 + 8 * lh16) * QSTRH + 8 * lh8) * 2;
    uint32_t pw_u   = smem_u32(Ps + warp * 16 * PSTRH);
    uint32_t pa_off = (uint32_t)((l7 + 8 * lh8) * PSTRH + 8 * lh16) * 2;
    uint32_t vb_off = (uint32_t)((l7 + 8 * lh8) * VSTRH + 8 * lh16) * 2;

#pragma unroll
    for (int j = 0; j < 12; j++) {
        int l = tid + j * 256, r = l / 24, e8 = l % 24;
        *(uint4*)(Qs + r * QSTRH + e8 * 8) =
            *(const uint4*)(qb + (size_t)(row0 + r) * EDIM + e8 * 8);
    }

    float o_acc[24][4];
#pragma unroll
    for (int nt = 0; nt < 24; nt++)
#pragma unroll
        for (int i = 0; i < 4; i++) o_acc[nt][i] = 0.f;
    float lsum0 = 0.f, lsum1 = 0.f;

    const float scl2 = 0.07216878364870322f * 1.4426950408889634f;
    __half* Pw = Ps + warp * 16 * PSTRH;

    {
#pragma unroll
        for (int j = 0; j < 3; j++) {
            int l = tid + j * 256, r = l / 24, e8 = l % 24;
            cp16(k_u[0] + (uint32_t)(r * QSTRH + e8 * 8) * 2, kb + (size_t)r * EDIM + e8 * 8);
            cp16(v_u[0] + (uint32_t)(r * VSTRH + e8 * 8) * 2, vb + (size_t)r * EDIM + e8 * 8);
        }
        CP_COMMIT();
        CP_WAITN(0);
    }
    __syncthreads();

    for (int t = 0; t < NKT; t++) {
        int cur = t & 1, nb = cur ^ 1;
        bool more = (t + 1 < NKT);

        if (more) {
            const __half* kbt = kb + (size_t)(t + 1) * KVT * EDIM;
            const __half* vbt = vb + (size_t)(t + 1) * KVT * EDIM;
#pragma unroll
            for (int j = 0; j < 3; j++) {
                int l = tid + j * 256, r = l / 24, e8 = l % 24;
                cp16(k_u[nb] + (uint32_t)(r * QSTRH + e8 * 8) * 2, kbt + (size_t)r * EDIM + e8 * 8);
                cp16(v_u[nb] + (uint32_t)(r * VSTRH + e8 * 8) * 2, vbt + (size_t)r * EDIM + e8 * 8);
            }
            CP_COMMIT();
        }

        float s[4][4];
#pragma unroll
        for (int nt = 0; nt < 4; nt++)
#pragma unroll
            for (int i = 0; i < 4; i++) s[nt][i] = 0.f;

#pragma unroll
        for (int ks = 0; ks < 12; ks++) {
            unsigned a[4];
            ldsm_x4(a, q_u + qa_off + (uint32_t)(16 * ks) * 2);
#pragma unroll
            for (int p = 0; p < 2; p++) {
                unsigned bb[4];
                ldsm_x4(bb, k_u[cur] + kb_off + (uint32_t)(16 * p * QSTRH + 16 * ks) * 2);
                mma_f16(s[2 * p],     a, bb);
                mma_f16(s[2 * p + 1], a, bb + 2);
            }
        }

#pragma unroll
        for (int nt = 0; nt < 4; nt++) {
            float p0 = exp2f(s[nt][0] * scl2);
            float p1 = exp2f(s[nt][1] * scl2);
            float p2 = exp2f(s[nt][2] * scl2);
            float p3 = exp2f(s[nt][3] * scl2);
            lsum0 += p0 + p1;
            lsum1 += p2 + p3;
            *(__half2*)(Pw + gID       * PSTRH + 8 * nt + 2 * tig) = __floats2half2_rn(p0, p1);
            *(__half2*)(Pw + (gID + 8) * PSTRH + 8 * nt + 2 * tig) = __floats2half2_rn(p2, p3);
        }
        __syncwarp();

#pragma unroll
        for (int kt = 0; kt < 2; kt++) {
            unsigned a[4];
            ldsm_x4(a, pw_u + pa_off + (uint32_t)(16 * kt) * 2);
#pragma unroll
            for (int g = 0; g < 12; g++) {
                unsigned vv[4];
                ldsm_x4_t(vv, v_u[cur] + vb_off + (uint32_t)(16 * kt * VSTRH + 16 * g) * 2);
                mma_f16(o_acc[2 * g],     a, vv);
                mma_f16(o_acc[2 * g + 1], a, vv + 2);
            }
        }

        if (more) CP_WAITN(0);
        __syncthreads();
    }

    lsum0 += __shfl_xor_sync(0xffffffffu, lsum0, 1);
    lsum0 += __shfl_xor_sync(0xffffffffu, lsum0, 2);
    lsum1 += __shfl_xor_sync(0xffffffffu, lsum1, 1);
    lsum1 += __shfl_xor_sync(0xffffffffu, lsum1, 2);
    float inv0 = 1.f / lsum0, inv1 = 1.f / lsum1;

    int n0 = row0 + m0 + gID;
    int n1 = n0 + 8;
    __half* d0 = g_ao + ((size_t)b * NSEQ + n0) * (DINNER * COOR) + h * EDIM;
    __half* d1 = g_ao + ((size_t)b * NSEQ + n1) * (DINNER * COOR) + h * EDIM;
#pragma unroll
    for (int nt = 0; nt < 24; nt++) {
#pragma unroll
        for (int hh = 0; hh < 2; hh++) {
            int e = 8 * nt + 2 * tig + hh;
            d0[e] = __float2half(o_acc[nt][hh]     * inv0);
            d1[e] = __float2half(o_acc[nt][2 + hh] * inv1);
        }
    }
}

// ===========================================================================
// Kernel 3: output projection (unchanged from R8)
// ===========================================================================
__global__ __launch_bounds__(384, 1) void oproj3_kernel(
    const float* __restrict__ Wo, float* __restrict__ out)
{
    extern __shared__ __half smh[];
    __half* As[2] = { smh, smh + 192 * AKH };
    __half* Ws[2] = { smh + 2 * 192 * AKH, smh + 2 * 192 * AKH + 64 * AKH };

    int bn0 = blockIdx.x * 64;
    int o0  = blockIdx.y * 64;
    int tid = threadIdx.x;
    int warp = tid >> 5, lane = tid & 31;
    int gID = lane >> 2, tig = lane & 3;
    int m0  = warp * 16;

    float o_acc[8][4];
#pragma unroll
    for (int nt = 0; nt < 8; nt++)
#pragma unroll
        for (int i = 0; i < 4; i++) o_acc[nt][i] = 0.f;

    const int NC = DINNER / 32;
    uint4 areg[2];
    float wreg[6];

#pragma unroll
    for (int j = 0; j < 2; j++) {
        int l = tid + j * 384, r = l / 12, q8 = l % 12;
        areg[j] = *(const uint4*)(g_ao + (size_t)(bn0 + r) * (DINNER * COOR) + q8 * 8);
    }
#pragma unroll
    for (int j = 0; j < 6; j++) {
        int l = tid + j * 384;
        if (l < 2048) { int o = l >> 5, k = l & 31; wreg[j] = Wo[(size_t)(o0 + o) * DINNER + k]; }
    }
#pragma unroll
    for (int j = 0; j < 2; j++) {
        int l = tid + j * 384, r = l / 12, q8 = l % 12;
        const __half* hv = (const __half*)&areg[j];
#pragma unroll
        for (int m = 0; m < 8; m++) {
            int p = q8 * 8 + m, k = p / 3, c = p - 3 * k;
            As[0][(c * 64 + r) * AKH + k] = hv[m];
        }
    }
#pragma unroll
    for (int j = 0; j < 6; j++) {
        int l = tid + j * 384;
        if (l < 2048) { int o = l >> 5, k = l & 31; Ws[0][o * AKH + k] = __float2half(wreg[j]); }
    }
    __syncthreads();

    for (int kc = 0; kc < NC; kc++) {
        int cur = kc & 1, nb = cur ^ 1;
        bool more = (kc + 1 < NC);
        if (more) {
            int k0 = (kc + 1) * 32;
#pragma unroll
            for (int j = 0; j < 2; j++) {
                int l = tid + j * 384, r = l / 12, q8 = l % 12;
                areg[j] = *(const uint4*)(g_ao + (size_t)(bn0 + r) * (DINNER * COOR) + k0 * 3 + q8 * 8);
            }
#pragma unroll
            for (int j = 0; j < 6; j++) {
                int l = tid + j * 384;
                if (l < 2048) { int o = l >> 5, k = l & 31; wreg[j] = Wo[(size_t)(o0 + o) * DINNER + k0 + k]; }
            }
        }

        const __half* A  = As[cur];
        const __half* Wt = Ws[cur];
#pragma unroll
        for (int ks = 0; ks < 2; ks++) {
            unsigned a[4];
            a[0] = *(const unsigned*)(A + (m0 + gID)     * AKH + 16 * ks + 2 * tig);
            a[1] = *(const unsigned*)(A + (m0 + gID + 8) * AKH + 16 * ks + 2 * tig);
            a[2] = *(const unsigned*)(A + (m0 + gID)     * AKH + 16 * ks + 2 * tig + 8);
            a[3] = *(const unsigned*)(A + (m0 + gID + 8) * AKH + 16 * ks + 2 * tig + 8);
#pragma unroll
            for (int nt = 0; nt < 8; nt++) {
                unsigned bf[2];
                bf[0] = *(const unsigned*)(Wt + (8 * nt + gID) * AKH + 16 * ks + 2 * tig);
                bf[1] = *(const unsigned*)(Wt + (8 * nt + gID) * AKH + 16 * ks + 2 * tig + 8);
                mma_f16(o_acc[nt], a, bf);
            }
        }

        if (more) {
#pragma unroll
            for (int j = 0; j < 2; j++) {
                int l = tid + j * 384, r = l / 12, q8 = l % 12;
                const __half* hv = (const __half*)&areg[j];
#pragma unroll
                for (int m = 0; m < 8; m++) {
                    int p = q8 * 8 + m, k = p / 3, c = p - 3 * k;
                    As[nb][(c * 64 + r) * AKH + k] = hv[m];
                }
            }
#pragma unroll
            for (int j = 0; j < 6; j++) {
                int l = tid + j * 384;
                if (l < 2048) { int o = l >> 5, k = l & 31; Ws[nb][o * AKH + k] = __float2half(wreg[j]); }
            }
        }
        __syncthreads();
    }

#pragma unroll
    for (int i = 0; i < 2; i++) {
        int arow = m0 + gID + 8 * i;
        int c = arow >> 6, bnl = arow & 63;
        int bn = bn0 + bnl;
#pragma unroll
        for (int nt = 0; nt < 8; nt++) {
#pragma unroll
            for (int hh = 0; hh < 2; hh++) {
                int o = o0 + 8 * nt + 2 * tig + hh;
                out[((size_t)bn * CIN + o) * 3 + c] = o_acc[nt][2 * i + hh];
            }
        }
    }
}

// ---------------------------------------------------------------------------
extern "C" void kernel_launch(void* const* d_in, const int* in_sizes, int n_in,
                              void* d_out, int out_size)
{
    const float* x  = (const float*)d_in[0];
    const float* Wq = (const float*)d_in[1];
    const float* Wk = (const float*)d_in[2];
    const float* Wv = (const float*)d_in[3];
    const float* Wo = (const float*)d_in[4];
    float* out = (float*)d_out;

    const int pj_smem   = (2 * 192 * AKH + 2 * 64 * AKH) * 2;
    const int qkv_smem  = QKV_SMEMH * 2;          // 82944 B
    const int attn_smem = SMTOT_H * 2;

    cudaFuncSetAttribute(qkv4_kernel,
                         cudaFuncAttributeMaxDynamicSharedMemorySize, qkv_smem);
    cudaFuncSetAttribute(attn4_kernel,
                         cudaFuncAttributeMaxDynamicSharedMemorySize, attn_smem);
    cudaFuncSetAttribute(oproj3_kernel,
                         cudaFuncAttributeMaxDynamicSharedMemorySize, pj_smem);

    conv_x_kernel<<<BN * CIN / 256, 256>>>(x);
    conv_w_kernel<<<3 * DINNER * CIN / 256, 256>>>(Wq, Wk, Wv);
    qkv4_kernel<<<dim3(BN / 128, DINNER / 64, 9), 256, qkv_smem>>>();
    attn4_kernel<<<dim3(NSEQ / 128, BDIM * HEADS), 256, attn_smem>>>();
    oproj3_kernel<<<dim3(BN / 64, CIN / 64), 384, pj_smem>>>(Wo, out);
}